// round 2
// baseline (speedup 1.0000x reference)
#include <cuda_runtime.h>
#include <cstdint>

// B=256, S=64, D=512, H=8, DK=DV=64, DFF=2048, IN=32768, OUT=50

// ---------------- device scratch (static, no allocation) ----------------
__device__ float g_q   [16384*512];
__device__ float g_k   [16384*512];
__device__ float g_v   [16384*512];
__device__ float g_ctx [16384*512];
__device__ float g_res1[16384*512];
__device__ float g_x   [16384*512];
__device__ float g_p4  [16*256*2048];
__device__ float g_h   [256*2048];
__device__ float g_v2  [256*32768];
__device__ float g_y   [256*32768];
__device__ float g_wfp [32768*64];
__device__ float g_p6  [64*256*64];

// ---------------- tf32 helpers ----------------
__device__ __forceinline__ uint32_t f2tf(float x) {
    uint32_t r;
    asm("cvt.rna.tf32.f32 %0, %1;" : "=r"(r) : "f"(x));
    return r;
}

__device__ __forceinline__ void mma_tf32(float* d, const uint32_t* a, const uint32_t* b) {
    asm volatile(
        "mma.sync.aligned.m16n8k8.row.col.f32.tf32.tf32.f32 "
        "{%0,%1,%2,%3},{%4,%5,%6,%7},{%8,%9},{%0,%1,%2,%3};"
        : "+f"(d[0]), "+f"(d[1]), "+f"(d[2]), "+f"(d[3])
        : "r"(a[0]), "r"(a[1]), "r"(a[2]), "r"(a[3]), "r"(b[0]), "r"(b[1]));
}

// ------------------------------------------------------------------
// Generic TF32 GEMM: C[?,N] = A @ B (+bias +resid, relu)
// BM=128 BN=64 BK=16, 256 thr (8 warps 4x2, warp tile 32x32)
// B(k, n0+jj) at B + blockIdx.y*bGroup + k*ldb + jj
// split-K: k0 = blockIdx.z*kChunk, C += blockIdx.z*cSplit
// ------------------------------------------------------------------
__global__ __launch_bounds__(256, 2) void gemm_tf32_k(
    const float* __restrict__ A, int lda,
    const float* __restrict__ B, int ldb, int bGroup,
    float* __restrict__ C, int ldc,
    int kIters, int kChunk, long cSplit,
    const float* __restrict__ bias,
    const float* __restrict__ resid,
    int relu)
{
    __shared__ uint32_t As[2][128*20];
    __shared__ uint32_t Bs[2][16*72];

    const int tid = threadIdx.x;
    const int m0 = blockIdx.x * 128;
    const int n0 = blockIdx.y * 64;
    const int k0 = blockIdx.z * kChunk;

    const float* Ap = A + (long)m0 * lda + k0;
    const float* Bp = B + (long)blockIdx.y * bGroup + (long)k0 * ldb;
    float* Cp = C + (long)blockIdx.z * cSplit;

    const int warp = tid >> 5, lane = tid & 31;
    const int wm = warp >> 1, wn = warp & 1;
    const int gid = lane >> 2, tg = lane & 3;

    const int ar = tid >> 2;          // 0..63 (A rows, +64 twin)
    const int ac = (tid & 3) * 4;     // 0,4,8,12
    const int br = tid >> 4;          // 0..15
    const int bc = (tid & 15) * 4;    // 0..60

    float acc[2][4][4];
#pragma unroll
    for (int i = 0; i < 2; i++)
#pragma unroll
        for (int j = 0; j < 4; j++)
#pragma unroll
            for (int l = 0; l < 4; l++) acc[i][j][l] = 0.f;

    float4 ra0, ra1, rb;
    ra0 = *(const float4*)(Ap + (long)ar * lda + ac);
    ra1 = *(const float4*)(Ap + (long)(ar + 64) * lda + ac);
    rb  = *(const float4*)(Bp + (long)br * ldb + bc);
    {
        uint4 u;
        u.x = f2tf(ra0.x); u.y = f2tf(ra0.y); u.z = f2tf(ra0.z); u.w = f2tf(ra0.w);
        *(uint4*)&As[0][ar * 20 + ac] = u;
        u.x = f2tf(ra1.x); u.y = f2tf(ra1.y); u.z = f2tf(ra1.z); u.w = f2tf(ra1.w);
        *(uint4*)&As[0][(ar + 64) * 20 + ac] = u;
        u.x = f2tf(rb.x);  u.y = f2tf(rb.y);  u.z = f2tf(rb.z);  u.w = f2tf(rb.w);
        *(uint4*)&Bs[0][br * 72 + bc] = u;
    }
    __syncthreads();

    for (int t = 0; t < kIters; t++) {
        if (t + 1 < kIters) {
            ra0 = *(const float4*)(Ap + (long)ar * lda + (t + 1) * 16 + ac);
            ra1 = *(const float4*)(Ap + (long)(ar + 64) * lda + (t + 1) * 16 + ac);
            rb  = *(const float4*)(Bp + (long)((t + 1) * 16 + br) * ldb + bc);
        }
        const uint32_t* as = As[t & 1];
        const uint32_t* bs = Bs[t & 1];
#pragma unroll
        for (int kk = 0; kk < 2; kk++) {
            const int kb = kk * 8;
            uint32_t af[2][4], bfr[4][2];
#pragma unroll
            for (int mt = 0; mt < 2; mt++) {
                int r = wm * 32 + mt * 16 + gid;
                af[mt][0] = as[r * 20 + kb + tg];
                af[mt][1] = as[(r + 8) * 20 + kb + tg];
                af[mt][2] = as[r * 20 + kb + tg + 4];
                af[mt][3] = as[(r + 8) * 20 + kb + tg + 4];
            }
#pragma unroll
            for (int nt = 0; nt < 4; nt++) {
                int c = wn * 32 + nt * 8 + gid;
                bfr[nt][0] = bs[(kb + tg) * 72 + c];
                bfr[nt][1] = bs[(kb + tg + 4) * 72 + c];
            }
#pragma unroll
            for (int mt = 0; mt < 2; mt++)
#pragma unroll
                for (int nt = 0; nt < 4; nt++)
                    mma_tf32(acc[mt][nt], af[mt], bfr[nt]);
        }
        if (t + 1 < kIters) {
            int st = (t + 1) & 1;
            uint4 u;
            u.x = f2tf(ra0.x); u.y = f2tf(ra0.y); u.z = f2tf(ra0.z); u.w = f2tf(ra0.w);
            *(uint4*)&As[st][ar * 20 + ac] = u;
            u.x = f2tf(ra1.x); u.y = f2tf(ra1.y); u.z = f2tf(ra1.z); u.w = f2tf(ra1.w);
            *(uint4*)&As[st][(ar + 64) * 20 + ac] = u;
            u.x = f2tf(rb.x);  u.y = f2tf(rb.y);  u.z = f2tf(rb.z);  u.w = f2tf(rb.w);
            *(uint4*)&Bs[st][br * 72 + bc] = u;
            __syncthreads();
        }
    }

#pragma unroll
    for (int mt = 0; mt < 2; mt++) {
        int r0 = m0 + wm * 32 + mt * 16 + gid;
#pragma unroll
        for (int nt = 0; nt < 4; nt++) {
            int col = n0 + wn * 32 + nt * 8 + tg * 2;
            float2 v0 = make_float2(acc[mt][nt][0], acc[mt][nt][1]);
            float2 v1 = make_float2(acc[mt][nt][2], acc[mt][nt][3]);
            if (bias) {
                float2 bv = *(const float2*)(bias + col);
                v0.x += bv.x; v0.y += bv.y; v1.x += bv.x; v1.y += bv.y;
            }
            if (resid) {
                float2 q0 = *(const float2*)(resid + (long)r0 * ldc + col);
                float2 q1 = *(const float2*)(resid + (long)(r0 + 8) * ldc + col);
                v0.x += q0.x; v0.y += q0.y; v1.x += q1.x; v1.y += q1.y;
            }
            if (relu) {
                v0.x = fmaxf(v0.x, 0.f); v0.y = fmaxf(v0.y, 0.f);
                v1.x = fmaxf(v1.x, 0.f); v1.y = fmaxf(v1.y, 0.f);
            }
            *(float2*)(Cp + (long)r0 * ldc + col) = v0;
            *(float2*)(Cp + (long)(r0 + 8) * ldc + col) = v1;
        }
    }
}

// ------------------------------------------------------------------
// Fused attention per (b,h): 64x64, fp32 SIMT, 256 threads
// q/k/v/ctx layout: row = b*64+s, col = h*64+e, ld=512
// ------------------------------------------------------------------
__global__ __launch_bounds__(256) void attn_k(
    const float* __restrict__ Q, const float* __restrict__ Kt,
    const float* __restrict__ V, float* __restrict__ Ctx)
{
    __shared__ float sA[64 * 68];
    __shared__ float sB[64 * 68];
    __shared__ float red[64];

    const int tid = threadIdx.x;
    const int b = blockIdx.x >> 3, h = blockIdx.x & 7;
    const long base = (long)b * 32768 + h * 64;

    for (int idx = tid; idx < 4096; idx += 256) {
        int s = idx >> 6, e = idx & 63;
        sA[s * 68 + e] = Q[base + (long)s * 512 + e];
        sB[s * 68 + e] = Kt[base + (long)s * 512 + e];
    }
    __syncthreads();

    const int ty = tid >> 4, tx = tid & 15;
    float sc[4][4] = {};
    for (int k = 0; k < 64; k += 4) {
        float4 qv[4], kv[4];
#pragma unroll
        for (int r = 0; r < 4; r++) qv[r] = *(const float4*)&sA[(4 * ty + r) * 68 + k];
#pragma unroll
        for (int c = 0; c < 4; c++) kv[c] = *(const float4*)&sB[(4 * tx + c) * 68 + k];
#pragma unroll
        for (int r = 0; r < 4; r++)
#pragma unroll
            for (int c = 0; c < 4; c++)
                sc[r][c] += qv[r].x * kv[c].x + qv[r].y * kv[c].y +
                            qv[r].z * kv[c].z + qv[r].w * kv[c].w;
    }
    __syncthreads();

#pragma unroll
    for (int r = 0; r < 4; r++) {
        float4 o = make_float4(sc[r][0] * 0.125f, sc[r][1] * 0.125f,
                               sc[r][2] * 0.125f, sc[r][3] * 0.125f);
        *(float4*)&sA[(4 * ty + r) * 68 + 4 * tx] = o;
    }
    for (int idx = tid; idx < 4096; idx += 256) {
        int s = idx >> 6, e = idx & 63;
        sB[s * 68 + e] = V[base + (long)s * 512 + e];
    }
    __syncthreads();

    if (tid < 64) {
        float m = -1e30f;
        for (int j = 0; j < 64; j++) m = fmaxf(m, sA[tid * 68 + j]);
        float sum = 0.f;
        for (int j = 0; j < 64; j++) {
            float e = __expf(sA[tid * 68 + j] - m);
            sA[tid * 68 + j] = e;
            sum += e;
        }
        red[tid] = 1.f / sum;
    }
    __syncthreads();

    float ct[4][4] = {};
    for (int j = 0; j < 64; j++) {
        float4 vv = *(const float4*)&sB[j * 68 + 4 * tx];
#pragma unroll
        for (int r = 0; r < 4; r++) {
            float p = sA[(4 * ty + r) * 68 + j];
            ct[r][0] += p * vv.x; ct[r][1] += p * vv.y;
            ct[r][2] += p * vv.z; ct[r][3] += p * vv.w;
        }
    }
#pragma unroll
    for (int r = 0; r < 4; r++) {
        float rs = red[4 * ty + r];
        float4 o = make_float4(ct[r][0] * rs, ct[r][1] * rs, ct[r][2] * rs, ct[r][3] * rs);
        *(float4*)(Ctx + base + (long)(4 * ty + r) * 512 + 4 * tx) = o;
    }
}

// ---------------- LayerNorm width=512, warp per row ----------------
__global__ __launch_bounds__(256) void ln512_k(
    const float* __restrict__ in, float* __restrict__ out,
    const float* __restrict__ gam, const float* __restrict__ bet)
{
    const int row = blockIdx.x * 8 + (threadIdx.x >> 5);
    const int lane = threadIdx.x & 31;
    const float* p = in + (long)row * 512;
    float v[16], s = 0.f, s2 = 0.f;
#pragma unroll
    for (int i = 0; i < 16; i++) {
        v[i] = p[lane + 32 * i];
        s += v[i];
        s2 = fmaf(v[i], v[i], s2);
    }
#pragma unroll
    for (int o = 16; o > 0; o >>= 1) {
        s  += __shfl_xor_sync(0xffffffffu, s, o);
        s2 += __shfl_xor_sync(0xffffffffu, s2, o);
    }
    float mu = s * (1.f / 512.f);
    float var = s2 * (1.f / 512.f) - mu * mu;
    float rsg = rsqrtf(var + 1e-5f);
    float* q = out + (long)row * 512;
#pragma unroll
    for (int i = 0; i < 16; i++) {
        int c = lane + 32 * i;
        q[c] = (v[i] - mu) * rsg * gam[c] + bet[c];
    }
}

// ---------------- LayerNorm width=32768, block per row ----------------
__global__ __launch_bounds__(1024) void ln32k_k(
    const float* __restrict__ in, float* __restrict__ out,
    const float* __restrict__ gam, const float* __restrict__ bet)
{
    __shared__ float rs1[32], rs2[32], stat[2];
    const int row = blockIdx.x;
    const float* p = in + (long)row * 32768;
    float s = 0.f, s2 = 0.f;
    for (int i = threadIdx.x; i < 32768; i += 1024) {
        float v = p[i];
        s += v;
        s2 = fmaf(v, v, s2);
    }
#pragma unroll
    for (int o = 16; o > 0; o >>= 1) {
        s  += __shfl_xor_sync(0xffffffffu, s, o);
        s2 += __shfl_xor_sync(0xffffffffu, s2, o);
    }
    if ((threadIdx.x & 31) == 0) {
        rs1[threadIdx.x >> 5] = s;
        rs2[threadIdx.x >> 5] = s2;
    }
    __syncthreads();
    if (threadIdx.x < 32) {
        s = rs1[threadIdx.x];
        s2 = rs2[threadIdx.x];
#pragma unroll
        for (int o = 16; o > 0; o >>= 1) {
            s  += __shfl_xor_sync(0xffffffffu, s, o);
            s2 += __shfl_xor_sync(0xffffffffu, s2, o);
        }
        if (threadIdx.x == 0) {
            float mu = s * (1.f / 32768.f);
            float var = s2 * (1.f / 32768.f) - mu * mu;
            stat[0] = mu;
            stat[1] = rsqrtf(var + 1e-5f);
        }
    }
    __syncthreads();
    float mu = stat[0], rsg = stat[1];
    float* q = out + (long)row * 32768;
    for (int i = threadIdx.x; i < 32768; i += 1024)
        q[i] = (p[i] - mu) * rsg * gam[i] + bet[i];
}

// ---------------- split-K reducers (fixed order, deterministic) ----------------
__global__ void reduce16_relu_k(const float* __restrict__ part,
                                const float* __restrict__ b1,
                                float* __restrict__ out)
{
    int idx = blockIdx.x * blockDim.x + threadIdx.x;  // < 256*2048
    float s = 0.f;
#pragma unroll
    for (int z = 0; z < 16; z++) s += part[(long)z * 524288 + idx];
    s += b1[idx & 2047];
    out[idx] = fmaxf(s, 0.f);
}

__global__ void reduce_out_k(const float* __restrict__ part,
                             const float* __restrict__ bf,
                             float* __restrict__ out)
{
    int idx = blockIdx.x * blockDim.x + threadIdx.x;
    if (idx >= 12800) return;
    int m = idx / 50, j = idx % 50;
    float s = bf[j];
#pragma unroll
    for (int z = 0; z < 64; z++) s += part[(long)z * 16384 + m * 64 + j];
    out[idx] = s;
}

// ---------------- pad Wf [32768,50] -> [32768,64] ----------------
__global__ void pad_wf_k(const float* __restrict__ Wf, float* __restrict__ Wfp)
{
    int idx = blockIdx.x * blockDim.x + threadIdx.x;  // < 32768*64
    int k = idx >> 6, j = idx & 63;
    Wfp[idx] = (j < 50) ? Wf[k * 50 + j] : 0.f;
}

// ------------------------------------------------------------------
extern "C" void kernel_launch(void* const* d_in, const int* in_sizes, int n_in,
                              void* d_out, int out_size)
{
    const float* inputs = (const float*)d_in[0];
    const float* Wq  = (const float*)d_in[1];
    const float* bq  = (const float*)d_in[2];
    const float* Wk  = (const float*)d_in[3];
    const float* bk  = (const float*)d_in[4];
    const float* Wv  = (const float*)d_in[5];
    const float* bv  = (const float*)d_in[6];
    const float* Wo  = (const float*)d_in[7];
    const float* bo  = (const float*)d_in[8];
    const float* ln1g = (const float*)d_in[9];
    const float* ln1b = (const float*)d_in[10];
    const float* W1  = (const float*)d_in[11];
    const float* b1  = (const float*)d_in[12];
    const float* W2  = (const float*)d_in[13];
    const float* b2  = (const float*)d_in[14];
    const float* ln2g = (const float*)d_in[15];
    const float* ln2b = (const float*)d_in[16];
    const float* Wf  = (const float*)d_in[17];
    const float* bf  = (const float*)d_in[18];
    float* out = (float*)d_out;

    float *q, *k, *v, *ctx, *res1, *x, *p4, *h, *v2, *y, *wfp, *p6;
    cudaGetSymbolAddress((void**)&q, g_q);
    cudaGetSymbolAddress((void**)&k, g_k);
    cudaGetSymbolAddress((void**)&v, g_v);
    cudaGetSymbolAddress((void**)&ctx, g_ctx);
    cudaGetSymbolAddress((void**)&res1, g_res1);
    cudaGetSymbolAddress((void**)&x, g_x);
    cudaGetSymbolAddress((void**)&p4, g_p4);
    cudaGetSymbolAddress((void**)&h, g_h);
    cudaGetSymbolAddress((void**)&v2, g_v2);
    cudaGetSymbolAddress((void**)&y, g_y);
    cudaGetSymbolAddress((void**)&wfp, g_wfp);
    cudaGetSymbolAddress((void**)&p6, g_p6);

    // Wf padding (independent)
    pad_wf_k<<<8192, 256>>>(Wf, wfp);

    // QKV projections: [16384,512] @ per-head [512,64] -> [16384, 8*64]
    gemm_tf32_k<<<dim3(128, 8, 1), 256>>>(inputs, 512, Wq, 64, 32768,
                                          q, 512, 32, 0, 0, bq, nullptr, 0);
    gemm_tf32_k<<<dim3(128, 8, 1), 256>>>(inputs, 512, Wk, 64, 32768,
                                          k, 512, 32, 0, 0, bk, nullptr, 0);
    gemm_tf32_k<<<dim3(128, 8, 1), 256>>>(inputs, 512, Wv, 64, 32768,
                                          v, 512, 32, 0, 0, bv, nullptr, 0);

    // attention per (b,h)
    attn_k<<<2048, 256>>>(q, k, v, ctx);

    // output projection + bias + residual(inputs)
    gemm_tf32_k<<<dim3(128, 8, 1), 256>>>(ctx, 512, Wo, 512, 64,
                                          res1, 512, 32, 0, 0, bo, inputs, 0);

    // LN1 -> x  (viewed as [256, 32768])
    ln512_k<<<2048, 256>>>(res1, x, ln1g, ln1b);

    // h = relu(x @ W1 + b1): M=256,N=2048,K=32768, split-K 16
    gemm_tf32_k<<<dim3(2, 32, 16), 256>>>(x, 32768, W1, 2048, 64,
                                          p4, 2048, 128, 2048, 524288,
                                          nullptr, nullptr, 0);
    reduce16_relu_k<<<2048, 256>>>(p4, b1, h);

    // v2 = h @ W2 + b2 + x: M=256,N=32768,K=2048
    gemm_tf32_k<<<dim3(2, 512, 1), 256>>>(h, 2048, W2, 32768, 64,
                                          v2, 32768, 128, 0, 0, b2, x, 0);

    // LN2 -> y
    ln32k_k<<<256, 1024>>>(v2, y, ln2g, ln2b);

    // logits partials: y @ wfp: M=256,N=64,K=32768, split-K 64
    gemm_tf32_k<<<dim3(2, 1, 64), 256>>>(y, 32768, wfp, 64, 64,
                                         p6, 64, 32, 512, 16384,
                                         nullptr, nullptr, 0);
    reduce_out_k<<<50, 256>>>(p6, bf, out);
}

// round 4
// speedup vs baseline: 1.0005x; 1.0005x over previous
#include <cuda_runtime.h>
#include <cstdint>

// B=256, S=64, D=512, H=8, DK=DV=64, DFF=2048, IN=32768, OUT=50

// ---------------- device scratch (static, no allocation) ----------------
__device__ float g_q   [16384*512];
__device__ float g_k   [16384*512];
__device__ float g_v   [16384*512];
__device__ float g_ctx [16384*512];
__device__ float g_res1[16384*512];
__device__ float g_x   [16384*512];
__device__ float g_p4  [16*256*2048];
__device__ float g_h   [256*2048];
__device__ float g_v2  [256*32768];
__device__ float g_y   [256*32768];
__device__ float g_wfp [32768*64];
__device__ float g_p6  [64*256*64];

// ---------------- tf32 helpers ----------------
__device__ __forceinline__ uint32_t f2tf(float x) {
    uint32_t r;
    asm("cvt.rna.tf32.f32 %0, %1;" : "=r"(r) : "f"(x));
    return r;
}

__device__ __forceinline__ void mma_tf32(float* d, const uint32_t* a, const uint32_t* b) {
    asm volatile(
        "mma.sync.aligned.m16n8k8.row.col.f32.tf32.tf32.f32 "
        "{%0,%1,%2,%3},{%4,%5,%6,%7},{%8,%9},{%0,%1,%2,%3};"
        : "+f"(d[0]), "+f"(d[1]), "+f"(d[2]), "+f"(d[3])
        : "r"(a[0]), "r"(a[1]), "r"(a[2]), "r"(a[3]), "r"(b[0]), "r"(b[1]));
}

// ------------------------------------------------------------------
// Generic TF32 GEMM: C[?,N] = A @ B (+bias +resid, relu)
// BM=128 BN=64 BK=16, 256 thr (8 warps 4x2, warp tile 32x32)
// B(k, n0+jj) at B + blockIdx.y*bGroup + k*ldb + jj
// split-K: k0 = blockIdx.z*kChunk, C += blockIdx.z*cSplit
// ------------------------------------------------------------------
__global__ __launch_bounds__(256, 2) void gemm_tf32_k(
    const float* __restrict__ A, int lda,
    const float* __restrict__ B, int ldb, int bGroup,
    float* __restrict__ C, int ldc,
    int kIters, int kChunk, long cSplit,
    const float* __restrict__ bias,
    const float* __restrict__ resid,
    int relu)
{
    __shared__ uint32_t As[2][128*20];
    __shared__ uint32_t Bs[2][16*72];

    const int tid = threadIdx.x;
    const int m0 = blockIdx.x * 128;
    const int n0 = blockIdx.y * 64;
    const int k0 = blockIdx.z * kChunk;

    const float* Ap = A + (long)m0 * lda + k0;
    const float* Bp = B + (long)blockIdx.y * bGroup + (long)k0 * ldb;
    float* Cp = C + (long)blockIdx.z * cSplit;

    const int warp = tid >> 5, lane = tid & 31;
    const int wm = warp >> 1, wn = warp & 1;
    const int gid = lane >> 2, tg = lane & 3;

    const int ar = tid >> 2;          // 0..63 (A rows, +64 twin)
    const int ac = (tid & 3) * 4;     // 0,4,8,12
    const int br = tid >> 4;          // 0..15
    const int bc = (tid & 15) * 4;    // 0..60

    float acc[2][4][4];
#pragma unroll
    for (int i = 0; i < 2; i++)
#pragma unroll
        for (int j = 0; j < 4; j++)
#pragma unroll
            for (int l = 0; l < 4; l++) acc[i][j][l] = 0.f;

    float4 ra0, ra1, rb;
    ra0 = *(const float4*)(Ap + (long)ar * lda + ac);
    ra1 = *(const float4*)(Ap + (long)(ar + 64) * lda + ac);
    rb  = *(const float4*)(Bp + (long)br * ldb + bc);
    {
        uint4 u;
        u.x = f2tf(ra0.x); u.y = f2tf(ra0.y); u.z = f2tf(ra0.z); u.w = f2tf(ra0.w);
        *(uint4*)&As[0][ar * 20 + ac] = u;
        u.x = f2tf(ra1.x); u.y = f2tf(ra1.y); u.z = f2tf(ra1.z); u.w = f2tf(ra1.w);
        *(uint4*)&As[0][(ar + 64) * 20 + ac] = u;
        u.x = f2tf(rb.x);  u.y = f2tf(rb.y);  u.z = f2tf(rb.z);  u.w = f2tf(rb.w);
        *(uint4*)&Bs[0][br * 72 + bc] = u;
    }
    __syncthreads();

    for (int t = 0; t < kIters; t++) {
        if (t + 1 < kIters) {
            ra0 = *(const float4*)(Ap + (long)ar * lda + (t + 1) * 16 + ac);
            ra1 = *(const float4*)(Ap + (long)(ar + 64) * lda + (t + 1) * 16 + ac);
            rb  = *(const float4*)(Bp + (long)((t + 1) * 16 + br) * ldb + bc);
        }
        const uint32_t* as = As[t & 1];
        const uint32_t* bs = Bs[t & 1];
#pragma unroll
        for (int kk = 0; kk < 2; kk++) {
            const int kb = kk * 8;
            uint32_t af[2][4], bfr[4][2];
#pragma unroll
            for (int mt = 0; mt < 2; mt++) {
                int r = wm * 32 + mt * 16 + gid;
                af[mt][0] = as[r * 20 + kb + tg];
                af[mt][1] = as[(r + 8) * 20 + kb + tg];
                af[mt][2] = as[r * 20 + kb + tg + 4];
                af[mt][3] = as[(r + 8) * 20 + kb + tg + 4];
            }
#pragma unroll
            for (int nt = 0; nt < 4; nt++) {
                int c = wn * 32 + nt * 8 + gid;
                bfr[nt][0] = bs[(kb + tg) * 72 + c];
                bfr[nt][1] = bs[(kb + tg + 4) * 72 + c];
            }
#pragma unroll
            for (int mt = 0; mt < 2; mt++)
#pragma unroll
                for (int nt = 0; nt < 4; nt++)
                    mma_tf32(acc[mt][nt], af[mt], bfr[nt]);
        }
        if (t + 1 < kIters) {
            int st = (t + 1) & 1;
            uint4 u;
            u.x = f2tf(ra0.x); u.y = f2tf(ra0.y); u.z = f2tf(ra0.z); u.w = f2tf(ra0.w);
            *(uint4*)&As[st][ar * 20 + ac] = u;
            u.x = f2tf(ra1.x); u.y = f2tf(ra1.y); u.z = f2tf(ra1.z); u.w = f2tf(ra1.w);
            *(uint4*)&As[st][(ar + 64) * 20 + ac] = u;
            u.x = f2tf(rb.x);  u.y = f2tf(rb.y);  u.z = f2tf(rb.z);  u.w = f2tf(rb.w);
            *(uint4*)&Bs[st][br * 72 + bc] = u;
            __syncthreads();
        }
    }

#pragma unroll
    for (int mt = 0; mt < 2; mt++) {
        int r0 = m0 + wm * 32 + mt * 16 + gid;
#pragma unroll
        for (int nt = 0; nt < 4; nt++) {
            int col = n0 + wn * 32 + nt * 8 + tg * 2;
            float2 v0 = make_float2(acc[mt][nt][0], acc[mt][nt][1]);
            float2 v1 = make_float2(acc[mt][nt][2], acc[mt][nt][3]);
            if (bias) {
                float2 bv = *(const float2*)(bias + col);
                v0.x += bv.x; v0.y += bv.y; v1.x += bv.x; v1.y += bv.y;
            }
            if (resid) {
                float2 q0 = *(const float2*)(resid + (long)r0 * ldc + col);
                float2 q1 = *(const float2*)(resid + (long)(r0 + 8) * ldc + col);
                v0.x += q0.x; v0.y += q0.y; v1.x += q1.x; v1.y += q1.y;
            }
            if (relu) {
                v0.x = fmaxf(v0.x, 0.f); v0.y = fmaxf(v0.y, 0.f);
                v1.x = fmaxf(v1.x, 0.f); v1.y = fmaxf(v1.y, 0.f);
            }
            *(float2*)(Cp + (long)r0 * ldc + col) = v0;
            *(float2*)(Cp + (long)(r0 + 8) * ldc + col) = v1;
        }
    }
}

// ------------------------------------------------------------------
// Fused attention per (b,h): 64x64, fp32 SIMT, 256 threads
// q/k/v/ctx layout: row = b*64+s, col = h*64+e, ld=512
// ------------------------------------------------------------------
__global__ __launch_bounds__(256) void attn_k(
    const float* __restrict__ Q, const float* __restrict__ Kt,
    const float* __restrict__ V, float* __restrict__ Ctx)
{
    __shared__ float sA[64 * 68];
    __shared__ float sB[64 * 68];
    __shared__ float red[64];

    const int tid = threadIdx.x;
    const int b = blockIdx.x >> 3, h = blockIdx.x & 7;
    const long base = (long)b * 32768 + h * 64;

    for (int idx = tid; idx < 4096; idx += 256) {
        int s = idx >> 6, e = idx & 63;
        sA[s * 68 + e] = Q[base + (long)s * 512 + e];
        sB[s * 68 + e] = Kt[base + (long)s * 512 + e];
    }
    __syncthreads();

    const int ty = tid >> 4, tx = tid & 15;
    float sc[4][4] = {};
    for (int k = 0; k < 64; k += 4) {
        float4 qv[4], kv[4];
#pragma unroll
        for (int r = 0; r < 4; r++) qv[r] = *(const float4*)&sA[(4 * ty + r) * 68 + k];
#pragma unroll
        for (int c = 0; c < 4; c++) kv[c] = *(const float4*)&sB[(4 * tx + c) * 68 + k];
#pragma unroll
        for (int r = 0; r < 4; r++)
#pragma unroll
            for (int c = 0; c < 4; c++)
                sc[r][c] += qv[r].x * kv[c].x + qv[r].y * kv[c].y +
                            qv[r].z * kv[c].z + qv[r].w * kv[c].w;
    }
    __syncthreads();

#pragma unroll
    for (int r = 0; r < 4; r++) {
        float4 o = make_float4(sc[r][0] * 0.125f, sc[r][1] * 0.125f,
                               sc[r][2] * 0.125f, sc[r][3] * 0.125f);
        *(float4*)&sA[(4 * ty + r) * 68 + 4 * tx] = o;
    }
    for (int idx = tid; idx < 4096; idx += 256) {
        int s = idx >> 6, e = idx & 63;
        sB[s * 68 + e] = V[base + (long)s * 512 + e];
    }
    __syncthreads();

    if (tid < 64) {
        float m = -1e30f;
        for (int j = 0; j < 64; j++) m = fmaxf(m, sA[tid * 68 + j]);
        float sum = 0.f;
        for (int j = 0; j < 64; j++) {
            float e = __expf(sA[tid * 68 + j] - m);
            sA[tid * 68 + j] = e;
            sum += e;
        }
        red[tid] = 1.f / sum;
    }
    __syncthreads();

    float ct[4][4] = {};
    for (int j = 0; j < 64; j++) {
        float4 vv = *(const float4*)&sB[j * 68 + 4 * tx];
#pragma unroll
        for (int r = 0; r < 4; r++) {
            float p = sA[(4 * ty + r) * 68 + j];
            ct[r][0] += p * vv.x; ct[r][1] += p * vv.y;
            ct[r][2] += p * vv.z; ct[r][3] += p * vv.w;
        }
    }
#pragma unroll
    for (int r = 0; r < 4; r++) {
        float rs = red[4 * ty + r];
        float4 o = make_float4(ct[r][0] * rs, ct[r][1] * rs, ct[r][2] * rs, ct[r][3] * rs);
        *(float4*)(Ctx + base + (long)(4 * ty + r) * 512 + 4 * tx) = o;
    }
}

// ---------------- LayerNorm width=512, warp per row ----------------
__global__ __launch_bounds__(256) void ln512_k(
    const float* __restrict__ in, float* __restrict__ out,
    const float* __restrict__ gam, const float* __restrict__ bet)
{
    const int row = blockIdx.x * 8 + (threadIdx.x >> 5);
    const int lane = threadIdx.x & 31;
    const float* p = in + (long)row * 512;
    float v[16], s = 0.f, s2 = 0.f;
#pragma unroll
    for (int i = 0; i < 16; i++) {
        v[i] = p[lane + 32 * i];
        s += v[i];
        s2 = fmaf(v[i], v[i], s2);
    }
#pragma unroll
    for (int o = 16; o > 0; o >>= 1) {
        s  += __shfl_xor_sync(0xffffffffu, s, o);
        s2 += __shfl_xor_sync(0xffffffffu, s2, o);
    }
    float mu = s * (1.f / 512.f);
    float var = s2 * (1.f / 512.f) - mu * mu;
    float rsg = rsqrtf(var + 1e-5f);
    float* q = out + (long)row * 512;
#pragma unroll
    for (int i = 0; i < 16; i++) {
        int c = lane + 32 * i;
        q[c] = (v[i] - mu) * rsg * gam[c] + bet[c];
    }
}

// ---------------- LayerNorm width=32768, block per row ----------------
__global__ __launch_bounds__(1024) void ln32k_k(
    const float* __restrict__ in, float* __restrict__ out,
    const float* __restrict__ gam, const float* __restrict__ bet)
{
    __shared__ float rs1[32], rs2[32], stat[2];
    const int row = blockIdx.x;
    const float* p = in + (long)row * 32768;
    float s = 0.f, s2 = 0.f;
    for (int i = threadIdx.x; i < 32768; i += 1024) {
        float v = p[i];
        s += v;
        s2 = fmaf(v, v, s2);
    }
#pragma unroll
    for (int o = 16; o > 0; o >>= 1) {
        s  += __shfl_xor_sync(0xffffffffu, s, o);
        s2 += __shfl_xor_sync(0xffffffffu, s2, o);
    }
    if ((threadIdx.x & 31) == 0) {
        rs1[threadIdx.x >> 5] = s;
        rs2[threadIdx.x >> 5] = s2;
    }
    __syncthreads();
    if (threadIdx.x < 32) {
        s = rs1[threadIdx.x];
        s2 = rs2[threadIdx.x];
#pragma unroll
        for (int o = 16; o > 0; o >>= 1) {
            s  += __shfl_xor_sync(0xffffffffu, s, o);
            s2 += __shfl_xor_sync(0xffffffffu, s2, o);
        }
        if (threadIdx.x == 0) {
            float mu = s * (1.f / 32768.f);
            float var = s2 * (1.f / 32768.f) - mu * mu;
            stat[0] = mu;
            stat[1] = rsqrtf(var + 1e-5f);
        }
    }
    __syncthreads();
    float mu = stat[0], rsg = stat[1];
    float* q = out + (long)row * 32768;
    for (int i = threadIdx.x; i < 32768; i += 1024)
        q[i] = (p[i] - mu) * rsg * gam[i] + bet[i];
}

// ---------------- split-K reducers (fixed order, deterministic) ----------------
__global__ void reduce16_relu_k(const float* __restrict__ part,
                                const float* __restrict__ b1,
                                float* __restrict__ out)
{
    int idx = blockIdx.x * blockDim.x + threadIdx.x;  // < 256*2048
    float s = 0.f;
#pragma unroll
    for (int z = 0; z < 16; z++) s += part[(long)z * 524288 + idx];
    s += b1[idx & 2047];
    out[idx] = fmaxf(s, 0.f);
}

__global__ void reduce_out_k(const float* __restrict__ part,
                             const float* __restrict__ bf,
                             float* __restrict__ out)
{
    int idx = blockIdx.x * blockDim.x + threadIdx.x;
    if (idx >= 12800) return;
    int m = idx / 50, j = idx % 50;
    float s = bf[j];
#pragma unroll
    for (int z = 0; z < 64; z++) s += part[(long)z * 16384 + m * 64 + j];
    out[idx] = s;
}

// ---------------- pad Wf [32768,50] -> [32768,64] ----------------
__global__ void pad_wf_k(const float* __restrict__ Wf, float* __restrict__ Wfp)
{
    int idx = blockIdx.x * blockDim.x + threadIdx.x;  // < 32768*64
    int k = idx >> 6, j = idx & 63;
    Wfp[idx] = (j < 50) ? Wf[k * 50 + j] : 0.f;
}

// ------------------------------------------------------------------
extern "C" void kernel_launch(void* const* d_in, const int* in_sizes, int n_in,
                              void* d_out, int out_size)
{
    const float* inputs = (const float*)d_in[0];
    const float* Wq  = (const float*)d_in[1];
    const float* bq  = (const float*)d_in[2];
    const float* Wk  = (const float*)d_in[3];
    const float* bk  = (const float*)d_in[4];
    const float* Wv  = (const float*)d_in[5];
    const float* bv  = (const float*)d_in[6];
    const float* Wo  = (const float*)d_in[7];
    const float* bo  = (const float*)d_in[8];
    const float* ln1g = (const float*)d_in[9];
    const float* ln1b = (const float*)d_in[10];
    const float* W1  = (const float*)d_in[11];
    const float* b1  = (const float*)d_in[12];
    const float* W2  = (const float*)d_in[13];
    const float* b2  = (const float*)d_in[14];
    const float* ln2g = (const float*)d_in[15];
    const float* ln2b = (const float*)d_in[16];
    const float* Wf  = (const float*)d_in[17];
    const float* bf  = (const float*)d_in[18];
    float* out = (float*)d_out;

    float *q, *k, *v, *ctx, *res1, *x, *p4, *h, *v2, *y, *wfp, *p6;
    cudaGetSymbolAddress((void**)&q, g_q);
    cudaGetSymbolAddress((void**)&k, g_k);
    cudaGetSymbolAddress((void**)&v, g_v);
    cudaGetSymbolAddress((void**)&ctx, g_ctx);
    cudaGetSymbolAddress((void**)&res1, g_res1);
    cudaGetSymbolAddress((void**)&x, g_x);
    cudaGetSymbolAddress((void**)&p4, g_p4);
    cudaGetSymbolAddress((void**)&h, g_h);
    cudaGetSymbolAddress((void**)&v2, g_v2);
    cudaGetSymbolAddress((void**)&y, g_y);
    cudaGetSymbolAddress((void**)&wfp, g_wfp);
    cudaGetSymbolAddress((void**)&p6, g_p6);

    // Wf padding (independent)
    pad_wf_k<<<8192, 256>>>(Wf, wfp);

    // QKV projections: [16384,512] @ per-head [512,64] -> [16384, 8*64]
    gemm_tf32_k<<<dim3(128, 8, 1), 256>>>(inputs, 512, Wq, 64, 32768,
                                          q, 512, 32, 0, 0, bq, nullptr, 0);
    gemm_tf32_k<<<dim3(128, 8, 1), 256>>>(inputs, 512, Wk, 64, 32768,
                                          k, 512, 32, 0, 0, bk, nullptr, 0);
    gemm_tf32_k<<<dim3(128, 8, 1), 256>>>(inputs, 512, Wv, 64, 32768,
                                          v, 512, 32, 0, 0, bv, nullptr, 0);

    // attention per (b,h)
    attn_k<<<2048, 256>>>(q, k, v, ctx);

    // output projection + bias + residual(inputs)
    gemm_tf32_k<<<dim3(128, 8, 1), 256>>>(ctx, 512, Wo, 512, 64,
                                          res1, 512, 32, 0, 0, bo, inputs, 0);

    // LN1 -> x  (viewed as [256, 32768])
    ln512_k<<<2048, 256>>>(res1, x, ln1g, ln1b);

    // h = relu(x @ W1 + b1): M=256,N=2048,K=32768, split-K 16
    gemm_tf32_k<<<dim3(2, 32, 16), 256>>>(x, 32768, W1, 2048, 64,
                                          p4, 2048, 128, 2048, 524288,
                                          nullptr, nullptr, 0);
    reduce16_relu_k<<<2048, 256>>>(p4, b1, h);

    // v2 = h @ W2 + b2 + x: M=256,N=32768,K=2048
    gemm_tf32_k<<<dim3(2, 512, 1), 256>>>(h, 2048, W2, 32768, 64,
                                          v2, 32768, 128, 0, 0, b2, x, 0);

    // LN2 -> y
    ln32k_k<<<256, 1024>>>(v2, y, ln2g, ln2b);

    // logits partials: y @ wfp: M=256,N=64,K=32768, split-K 64
    gemm_tf32_k<<<dim3(2, 1, 64), 256>>>(y, 32768, wfp, 64, 64,
                                         p6, 64, 32, 512, 16384,
                                         nullptr, nullptr, 0);
    reduce_out_k<<<50, 256>>>(p6, bf, out);
}

// round 8
// speedup vs baseline: 1.5742x; 1.5733x over previous
#include <cuda_runtime.h>
#include <cuda_fp16.h>
#include <cstdint>

// B=256, S=64, D=512, H=8, DK=DV=64, DFF=2048, IN=32768, OUT=50

// ---------------- device scratch (static, no allocation) ----------------
__device__ float g_q   [16384L*512];
__device__ float g_k   [16384L*512];
__device__ float g_v   [16384L*512];
__device__ float g_ctx [16384L*512];
__device__ float g_res1[16384L*512];
__device__ float g_x   [16384L*512];
__device__ float g_p4  [16L*256*2048];
__device__ float g_h   [256L*2048];
__device__ float g_v2  [256L*32768];
__device__ float g_y   [256L*32768];
__device__ float g_wfp [32768L*64];
__device__ float g_p6  [64L*256*64];

// ---------------- fp16 helpers ----------------
__device__ __forceinline__ uint32_t pack2(float a, float b) {
    __half2 h = __floats2half2_rn(a, b);
    return *reinterpret_cast<uint32_t*>(&h);
}

// A smem layout: 128 rows x 32 halves (64B/row), two rows share a 128B atom,
// 16B chunks XOR-swizzled by atom index (conflict-free for ldmatrix + STS.128).
__device__ __forceinline__ int aoff(int r, int c) {   // c = 16B chunk 0..3
    return ((r >> 1) << 7) + (((((r & 1) << 2) + c) ^ ((r >> 1) & 7)) << 4);
}
// B smem layout: 32 rows x 64 halves (128B/row), native SW128 swizzle.
__device__ __forceinline__ int boff(int k, int c) {   // c = 16B chunk 0..7
    return (k << 7) + (((c ^ (k & 7)) & 7) << 4);
}

__device__ __forceinline__ void ldsm_x4(uint32_t* r, uint32_t addr) {
    asm volatile("ldmatrix.sync.aligned.m8n8.x4.shared.b16 {%0,%1,%2,%3}, [%4];"
                 : "=r"(r[0]), "=r"(r[1]), "=r"(r[2]), "=r"(r[3]) : "r"(addr));
}
__device__ __forceinline__ void ldsm_x4_t(uint32_t* r, uint32_t addr) {
    asm volatile("ldmatrix.sync.aligned.m8n8.x4.trans.shared.b16 {%0,%1,%2,%3}, [%4];"
                 : "=r"(r[0]), "=r"(r[1]), "=r"(r[2]), "=r"(r[3]) : "r"(addr));
}
__device__ __forceinline__ void mma_fp16(float* d, const uint32_t* a, const uint32_t* b) {
    asm volatile(
        "mma.sync.aligned.m16n8k16.row.col.f32.f16.f16.f32 "
        "{%0,%1,%2,%3},{%4,%5,%6,%7},{%8,%9},{%0,%1,%2,%3};"
        : "+f"(d[0]), "+f"(d[1]), "+f"(d[2]), "+f"(d[3])
        : "r"(a[0]), "r"(a[1]), "r"(a[2]), "r"(a[3]), "r"(b[0]), "r"(b[1]));
}
__device__ __forceinline__ uint32_t smem_u32(const void* p) {
    uint32_t a;
    asm("{ .reg .u64 t; cvta.to.shared.u64 t, %1; cvt.u32.u64 %0, t; }" : "=r"(a) : "l"(p));
    return a;
}

// ------------------------------------------------------------------
// FP16 GEMM via mma.sync.m16n8k16 + ldmatrix.
// C[?,N] = A @ B (+bias +resid, relu); fp32 in/out, fp16 operands, fp32 acc.
// BM=128 BN=64 BK=32, 256 thr (8 warps 4x2, warp tile 32x32), double-buffered.
// B(k, n0+jj) at B + blockIdx.y*bGroup + k*ldb + jj
// split-K: k0 = blockIdx.z*kChunk, C += blockIdx.z*cSplit
// ------------------------------------------------------------------
__global__ __launch_bounds__(256, 2) void gemm_fp16_k(
    const float* __restrict__ A, int lda,
    const float* __restrict__ B, int ldb, int bGroup,
    float* __restrict__ C, int ldc,
    int kIters, int kChunk, long cSplit,
    const float* __restrict__ bias,
    const float* __restrict__ resid,
    int relu)
{
    constexpr int ABYTES = 128 * 64;   // 8192
    constexpr int BBYTES = 32 * 128;   // 4096
    __shared__ char sm[2][ABYTES + BBYTES];

    const int tid = threadIdx.x;
    const int m0 = blockIdx.x * 128;
    const int n0 = blockIdx.y * 64;
    const int k0 = blockIdx.z * kChunk;

    const float* Ap = A + (long)m0 * lda + k0;
    const float* Bp = B + (long)blockIdx.y * bGroup + (long)k0 * ldb;
    float* Cp = C + (long)blockIdx.z * cSplit;

    const int warp = tid >> 5, lane = tid & 31;
    const int wm = warp >> 1, wn = warp & 1;
    const int gid = lane >> 2, tg = lane & 3;

    // staging assignments
    const int ar = tid >> 2;          // A rows: ar and ar+64
    const int ac = tid & 3;           // A 16B chunk (8 fp32 cols each)
    const int br = tid >> 3;          // B row (k), 0..31
    const int bc = tid & 7;           // B 16B chunk (8 fp32 cols)

    // ldmatrix source addresses (fixed per thread, per buffer)
    //  A (per mt, per kk): row = wm*32 + mt*16 + (lane&15), chunk = kk*2 + (lane>>4)
    const int aRowL = (lane & 15);
    const int aChL  = (lane >> 4);
    //  B (per ntp, per kk): row = kk*16 + (lane&15), chunk = wn*4 + ntp*2 + (lane>>4)
    uint32_t sbase[2] = { smem_u32(&sm[0][0]), smem_u32(&sm[1][0]) };

    float acc[2][4][4];
#pragma unroll
    for (int i = 0; i < 2; i++)
#pragma unroll
        for (int j = 0; j < 4; j++)
#pragma unroll
            for (int l = 0; l < 4; l++) acc[i][j][l] = 0.f;

    float4 ra0a, ra0b, ra1a, ra1b, rb0, rb1;

    // ---- prologue: stage tile 0
    ra0a = *(const float4*)(Ap + (long)ar * lda + ac * 8);
    ra0b = *(const float4*)(Ap + (long)ar * lda + ac * 8 + 4);
    ra1a = *(const float4*)(Ap + (long)(ar + 64) * lda + ac * 8);
    ra1b = *(const float4*)(Ap + (long)(ar + 64) * lda + ac * 8 + 4);
    rb0  = *(const float4*)(Bp + (long)br * ldb + bc * 8);
    rb1  = *(const float4*)(Bp + (long)br * ldb + bc * 8 + 4);
    {
        uint4 u;
        u.x = pack2(ra0a.x, ra0a.y); u.y = pack2(ra0a.z, ra0a.w);
        u.z = pack2(ra0b.x, ra0b.y); u.w = pack2(ra0b.z, ra0b.w);
        *(uint4*)&sm[0][aoff(ar, ac)] = u;
        u.x = pack2(ra1a.x, ra1a.y); u.y = pack2(ra1a.z, ra1a.w);
        u.z = pack2(ra1b.x, ra1b.y); u.w = pack2(ra1b.z, ra1b.w);
        *(uint4*)&sm[0][aoff(ar + 64, ac)] = u;
        u.x = pack2(rb0.x, rb0.y); u.y = pack2(rb0.z, rb0.w);
        u.z = pack2(rb1.x, rb1.y); u.w = pack2(rb1.z, rb1.w);
        *(uint4*)&sm[0][ABYTES + boff(br, bc)] = u;
    }
    __syncthreads();

    for (int t = 0; t < kIters; t++) {
        if (t + 1 < kIters) {
            const long kb = (long)(t + 1) * 32;
            ra0a = *(const float4*)(Ap + (long)ar * lda + kb + ac * 8);
            ra0b = *(const float4*)(Ap + (long)ar * lda + kb + ac * 8 + 4);
            ra1a = *(const float4*)(Ap + (long)(ar + 64) * lda + kb + ac * 8);
            ra1b = *(const float4*)(Ap + (long)(ar + 64) * lda + kb + ac * 8 + 4);
            rb0  = *(const float4*)(Bp + (long)(kb + br) * ldb + bc * 8);
            rb1  = *(const float4*)(Bp + (long)(kb + br) * ldb + bc * 8 + 4);
        }
        const uint32_t sa = sbase[t & 1];
        const uint32_t sbB = sbase[t & 1] + ABYTES;
#pragma unroll
        for (int kk = 0; kk < 2; kk++) {
            uint32_t af[2][4], bf[2][4];
#pragma unroll
            for (int mt = 0; mt < 2; mt++)
                ldsm_x4(af[mt], sa + aoff(wm * 32 + mt * 16 + aRowL, kk * 2 + aChL));
#pragma unroll
            for (int ntp = 0; ntp < 2; ntp++)
                ldsm_x4_t(bf[ntp], sbB + boff(kk * 16 + aRowL, wn * 4 + ntp * 2 + aChL));
#pragma unroll
            for (int mt = 0; mt < 2; mt++) {
#pragma unroll
                for (int ntp = 0; ntp < 2; ntp++) {
                    mma_fp16(acc[mt][ntp * 2 + 0], af[mt], &bf[ntp][0]);
                    mma_fp16(acc[mt][ntp * 2 + 1], af[mt], &bf[ntp][2]);
                }
            }
        }
        if (t + 1 < kIters) {
            char* d = sm[(t + 1) & 1];
            uint4 u;
            u.x = pack2(ra0a.x, ra0a.y); u.y = pack2(ra0a.z, ra0a.w);
            u.z = pack2(ra0b.x, ra0b.y); u.w = pack2(ra0b.z, ra0b.w);
            *(uint4*)&d[aoff(ar, ac)] = u;
            u.x = pack2(ra1a.x, ra1a.y); u.y = pack2(ra1a.z, ra1a.w);
            u.z = pack2(ra1b.x, ra1b.y); u.w = pack2(ra1b.z, ra1b.w);
            *(uint4*)&d[aoff(ar + 64, ac)] = u;
            u.x = pack2(rb0.x, rb0.y); u.y = pack2(rb0.z, rb0.w);
            u.z = pack2(rb1.x, rb1.y); u.w = pack2(rb1.z, rb1.w);
            *(uint4*)&d[ABYTES + boff(br, bc)] = u;
            __syncthreads();
        }
    }

    // ---- epilogue (same C fragment layout as m16n8 tf32)
#pragma unroll
    for (int mt = 0; mt < 2; mt++) {
        int r0 = m0 + wm * 32 + mt * 16 + gid;
#pragma unroll
        for (int nt = 0; nt < 4; nt++) {
            int col = n0 + wn * 32 + nt * 8 + tg * 2;
            float2 v0 = make_float2(acc[mt][nt][0], acc[mt][nt][1]);
            float2 v1 = make_float2(acc[mt][nt][2], acc[mt][nt][3]);
            if (bias) {
                float2 bv = *(const float2*)(bias + col);
                v0.x += bv.x; v0.y += bv.y; v1.x += bv.x; v1.y += bv.y;
            }
            if (resid) {
                float2 q0 = *(const float2*)(resid + (long)r0 * ldc + col);
                float2 q1 = *(const float2*)(resid + (long)(r0 + 8) * ldc + col);
                v0.x += q0.x; v0.y += q0.y; v1.x += q1.x; v1.y += q1.y;
            }
            if (relu) {
                v0.x = fmaxf(v0.x, 0.f); v0.y = fmaxf(v0.y, 0.f);
                v1.x = fmaxf(v1.x, 0.f); v1.y = fmaxf(v1.y, 0.f);
            }
            *(float2*)(Cp + (long)r0 * ldc + col) = v0;
            *(float2*)(Cp + (long)(r0 + 8) * ldc + col) = v1;
        }
    }
}

// ------------------------------------------------------------------
// Fused attention per (b,h): 64x64, fp32 SIMT, 256 threads (unchanged)
// ------------------------------------------------------------------
__global__ __launch_bounds__(256) void attn_k(
    const float* __restrict__ Q, const float* __restrict__ Kt,
    const float* __restrict__ V, float* __restrict__ Ctx)
{
    __shared__ float sA[64 * 68];
    __shared__ float sB[64 * 68];
    __shared__ float red[64];

    const int tid = threadIdx.x;
    const int b = blockIdx.x >> 3, h = blockIdx.x & 7;
    const long base = (long)b * 32768 + h * 64;

    for (int idx = tid; idx < 4096; idx += 256) {
        int s = idx >> 6, e = idx & 63;
        sA[s * 68 + e] = Q[base + (long)s * 512 + e];
        sB[s * 68 + e] = Kt[base + (long)s * 512 + e];
    }
    __syncthreads();

    const int ty = tid >> 4, tx = tid & 15;
    float sc[4][4] = {};
    for (int k = 0; k < 64; k += 4) {
        float4 qv[4], kv[4];
#pragma unroll
        for (int r = 0; r < 4; r++) qv[r] = *(const float4*)&sA[(4 * ty + r) * 68 + k];
#pragma unroll
        for (int c = 0; c < 4; c++) kv[c] = *(const float4*)&sB[(4 * tx + c) * 68 + k];
#pragma unroll
        for (int r = 0; r < 4; r++)
#pragma unroll
            for (int c = 0; c < 4; c++)
                sc[r][c] += qv[r].x * kv[c].x + qv[r].y * kv[c].y +
                            qv[r].z * kv[c].z + qv[r].w * kv[c].w;
    }
    __syncthreads();

#pragma unroll
    for (int r = 0; r < 4; r++)
        *(float4*)&sA[(4 * ty + r) * 68 + 4 * tx] =
            make_float4(sc[r][0] * 0.125f, sc[r][1] * 0.125f,
                        sc[r][2] * 0.125f, sc[r][3] * 0.125f);
    for (int idx = tid; idx < 4096; idx += 256) {
        int s = idx >> 6, e = idx & 63;
        sB[s * 68 + e] = V[base + (long)s * 512 + e];
    }
    __syncthreads();

    if (tid < 64) {
        float m = -1e30f;
        for (int j = 0; j < 64; j++) m = fmaxf(m, sA[tid * 68 + j]);
        float sum = 0.f;
        for (int j = 0; j < 64; j++) {
            float e = __expf(sA[tid * 68 + j] - m);
            sA[tid * 68 + j] = e; sum += e;
        }
        red[tid] = 1.f / sum;
    }
    __syncthreads();

    float ct[4][4] = {};
    for (int j = 0; j < 64; j++) {
        float4 vv = *(const float4*)&sB[j * 68 + 4 * tx];
#pragma unroll
        for (int r = 0; r < 4; r++) {
            float p = sA[(4 * ty + r) * 68 + j];
            ct[r][0] += p * vv.x; ct[r][1] += p * vv.y;
            ct[r][2] += p * vv.z; ct[r][3] += p * vv.w;
        }
    }
#pragma unroll
    for (int r = 0; r < 4; r++) {
        float rs = red[4 * ty + r];
        *(float4*)(Ctx + base + (long)(4 * ty + r) * 512 + 4 * tx) =
            make_float4(ct[r][0] * rs, ct[r][1] * rs, ct[r][2] * rs, ct[r][3] * rs);
    }
}

// ---------------- LayerNorm width=512, warp per row ----------------
__global__ __launch_bounds__(256) void ln512_k(
    const float* __restrict__ in, float* __restrict__ out,
    const float* __restrict__ gam, const float* __restrict__ bet)
{
    const int row = blockIdx.x * 8 + (threadIdx.x >> 5);
    const int lane = threadIdx.x & 31;
    const float* p = in + (long)row * 512;
    float v[16], s = 0.f, s2 = 0.f;
#pragma unroll
    for (int i = 0; i < 16; i++) {
        v[i] = p[lane + 32 * i]; s += v[i]; s2 = fmaf(v[i], v[i], s2);
    }
#pragma unroll
    for (int o = 16; o > 0; o >>= 1) {
        s += __shfl_xor_sync(~0u, s, o); s2 += __shfl_xor_sync(~0u, s2, o);
    }
    float mu = s * (1.f / 512.f);
    float rsg = rsqrtf(s2 * (1.f / 512.f) - mu * mu + 1e-5f);
    float* q = out + (long)row * 512;
#pragma unroll
    for (int i = 0; i < 16; i++) {
        int c = lane + 32 * i;
        q[c] = (v[i] - mu) * rsg * gam[c] + bet[c];
    }
}

// ---------------- LayerNorm width=32768, block per row ----------------
__global__ __launch_bounds__(1024) void ln32k_k(
    const float* __restrict__ in, float* __restrict__ out,
    const float* __restrict__ gam, const float* __restrict__ bet)
{
    __shared__ float rs1[32], rs2[32], stat[2];
    const int row = blockIdx.x;
    const float* p = in + (long)row * 32768;
    float s = 0.f, s2 = 0.f;
    for (int i = threadIdx.x; i < 32768; i += 1024) {
        float v = p[i]; s += v; s2 = fmaf(v, v, s2);
    }
#pragma unroll
    for (int o = 16; o > 0; o >>= 1) {
        s += __shfl_xor_sync(~0u, s, o); s2 += __shfl_xor_sync(~0u, s2, o);
    }
    if ((threadIdx.x & 31) == 0) { rs1[threadIdx.x >> 5] = s; rs2[threadIdx.x >> 5] = s2; }
    __syncthreads();
    if (threadIdx.x < 32) {
        s = rs1[threadIdx.x]; s2 = rs2[threadIdx.x];
#pragma unroll
        for (int o = 16; o > 0; o >>= 1) {
            s += __shfl_xor_sync(~0u, s, o); s2 += __shfl_xor_sync(~0u, s2, o);
        }
        if (threadIdx.x == 0) {
            float mu = s * (1.f / 32768.f);
            stat[0] = mu; stat[1] = rsqrtf(s2 * (1.f / 32768.f) - mu * mu + 1e-5f);
        }
    }
    __syncthreads();
    float mu = stat[0], rsg = stat[1];
    float* q = out + (long)row * 32768;
    for (int i = threadIdx.x; i < 32768; i += 1024)
        q[i] = (p[i] - mu) * rsg * gam[i] + bet[i];
}

// ---------------- split-K reducers (fixed order, deterministic) ----------------
__global__ void reduce16_relu_k(const float* __restrict__ part,
                                const float* __restrict__ b1,
                                float* __restrict__ out)
{
    int idx = blockIdx.x * blockDim.x + threadIdx.x;  // < 256*2048
    float s = 0.f;
#pragma unroll
    for (int z = 0; z < 16; z++) s += part[(long)z * 524288 + idx];
    s += b1[idx & 2047];
    out[idx] = fmaxf(s, 0.f);
}

__global__ void reduce_out_k(const float* __restrict__ part,
                             const float* __restrict__ bf,
                             float* __restrict__ out)
{
    int idx = blockIdx.x * blockDim.x + threadIdx.x;
    if (idx >= 12800) return;
    int m = idx / 50, j = idx % 50;
    float s = bf[j];
#pragma unroll
    for (int z = 0; z < 64; z++) s += part[(long)z * 16384 + m * 64 + j];
    out[idx] = s;
}

// ---------------- pad Wf [32768,50] -> [32768,64] ----------------
__global__ void pad_wf_k(const float* __restrict__ Wf, float* __restrict__ Wfp)
{
    int idx = blockIdx.x * blockDim.x + threadIdx.x;  // < 32768*64
    int k = idx >> 6, j = idx & 63;
    Wfp[idx] = (j < 50) ? Wf[k * 50 + j] : 0.f;
}

// ------------------------------------------------------------------
extern "C" void kernel_launch(void* const* d_in, const int* in_sizes, int n_in,
                              void* d_out, int out_size)
{
    const float* inputs = (const float*)d_in[0];
    const float* Wq = (const float*)d_in[1];  const float* bq = (const float*)d_in[2];
    const float* Wk = (const float*)d_in[3];  const float* bk = (const float*)d_in[4];
    const float* Wv = (const float*)d_in[5];  const float* bv = (const float*)d_in[6];
    const float* Wo = (const float*)d_in[7];  const float* bo = (const float*)d_in[8];
    const float* ln1g = (const float*)d_in[9];  const float* ln1b = (const float*)d_in[10];
    const float* W1 = (const float*)d_in[11]; const float* b1 = (const float*)d_in[12];
    const float* W2 = (const float*)d_in[13]; const float* b2 = (const float*)d_in[14];
    const float* ln2g = (const float*)d_in[15]; const float* ln2b = (const float*)d_in[16];
    const float* Wf = (const float*)d_in[17]; const float* bf = (const float*)d_in[18];
    float* out = (float*)d_out;

    float *q, *k, *v, *ctx, *res1, *x, *p4, *h, *v2, *y, *wfp, *p6;
    cudaGetSymbolAddress((void**)&q, g_q);
    cudaGetSymbolAddress((void**)&k, g_k);
    cudaGetSymbolAddress((void**)&v, g_v);
    cudaGetSymbolAddress((void**)&ctx, g_ctx);
    cudaGetSymbolAddress((void**)&res1, g_res1);
    cudaGetSymbolAddress((void**)&x, g_x);
    cudaGetSymbolAddress((void**)&p4, g_p4);
    cudaGetSymbolAddress((void**)&h, g_h);
    cudaGetSymbolAddress((void**)&v2, g_v2);
    cudaGetSymbolAddress((void**)&y, g_y);
    cudaGetSymbolAddress((void**)&wfp, g_wfp);
    cudaGetSymbolAddress((void**)&p6, g_p6);

    // Wf padding (independent)
    pad_wf_k<<<8192, 256>>>(Wf, wfp);

    // QKV projections: [16384,512] @ per-head [512,64] -> [16384, 8*64]
    gemm_fp16_k<<<dim3(128, 8, 1), 256>>>(inputs, 512, Wq, 64, 32768,
                                          q, 512, 16, 0, 0, bq, nullptr, 0);
    gemm_fp16_k<<<dim3(128, 8, 1), 256>>>(inputs, 512, Wk, 64, 32768,
                                          k, 512, 16, 0, 0, bk, nullptr, 0);
    gemm_fp16_k<<<dim3(128, 8, 1), 256>>>(inputs, 512, Wv, 64, 32768,
                                          v, 512, 16, 0, 0, bv, nullptr, 0);

    // attention per (b,h)
    attn_k<<<2048, 256>>>(q, k, v, ctx);

    // output projection + bias + residual(inputs)
    gemm_fp16_k<<<dim3(128, 8, 1), 256>>>(ctx, 512, Wo, 512, 64,
                                          res1, 512, 16, 0, 0, bo, inputs, 0);

    // LN1 -> x (viewed as [256, 32768])
    ln512_k<<<2048, 256>>>(res1, x, ln1g, ln1b);

    // h = relu(x @ W1 + b1): M=256,N=2048,K=32768, split-K 16
    gemm_fp16_k<<<dim3(2, 32, 16), 256>>>(x, 32768, W1, 2048, 64,
                                          p4, 2048, 64, 2048, 524288,
                                          nullptr, nullptr, 0);
    reduce16_relu_k<<<2048, 256>>>(p4, b1, h);

    // v2 = h @ W2 + b2 + x: M=256,N=32768,K=2048
    gemm_fp16_k<<<dim3(2, 512, 1), 256>>>(h, 2048, W2, 32768, 64,
                                          v2, 32768, 64, 0, 0, b2, x, 0);

    // LN2 -> y
    ln32k_k<<<256, 1024>>>(v2, y, ln2g, ln2b);

    // logits partials: y @ wfp: M=256,N=64,K=32768, split-K 64
    gemm_fp16_k<<<dim3(2, 1, 64), 256>>>(y, 32768, wfp, 64, 64,
                                         p6, 64, 16, 512, 16384,
                                         nullptr, nullptr, 0);
    reduce_out_k<<<50, 256>>>(p6, bf, out);
}

// round 9
// speedup vs baseline: 2.0198x; 1.2831x over previous
#include <cuda_runtime.h>
#include <cuda_fp16.h>
#include <cstdint>

// B=256, S=64, D=512, H=8, DK=DV=64, DFF=2048, IN=32768, OUT=50

// ---------------- device scratch (static, no allocation) ----------------
__device__ float g_q   [16384L*512];
__device__ float g_k   [16384L*512];
__device__ float g_v   [16384L*512];
__device__ float g_ctx [16384L*512];
__device__ float g_res1[16384L*512];
__device__ float g_x   [16384L*512];
__device__ float g_p4  [16L*256*2048];
__device__ float g_h   [256L*2048];
__device__ float g_v2  [256L*32768];
__device__ float g_y   [256L*32768];
__device__ float g_wfp [32768L*64];
__device__ float g_p6  [64L*256*64];

// ---------------- fp16 helpers ----------------
__device__ __forceinline__ uint32_t pack2(float a, float b) {
    __half2 h = __floats2half2_rn(a, b);
    return *reinterpret_cast<uint32_t*>(&h);
}

// A smem: 128 rows x 32 halves (64B/row), 2 rows per 128B atom, XOR swizzle.
__device__ __forceinline__ int aoff(int r, int c) {   // c = 16B chunk 0..3
    return ((r >> 1) << 7) + (((((r & 1) << 2) + c) ^ ((r >> 1) & 7)) << 4);
}
// B smem: 32 rows x BN halves (2*BN bytes/row), XOR swizzle on low 3 chunk bits.
template<int BN>
__device__ __forceinline__ int boff(int k, int c) {   // c = 16B chunk 0..BN/8-1
    return k * (2 * BN) + ((((c & ~7) | ((c ^ (k & 7)) & 7))) << 4);
}

__device__ __forceinline__ void ldsm_x4(uint32_t* r, uint32_t addr) {
    asm volatile("ldmatrix.sync.aligned.m8n8.x4.shared.b16 {%0,%1,%2,%3}, [%4];"
                 : "=r"(r[0]), "=r"(r[1]), "=r"(r[2]), "=r"(r[3]) : "r"(addr));
}
__device__ __forceinline__ void ldsm_x4_t(uint32_t* r, uint32_t addr) {
    asm volatile("ldmatrix.sync.aligned.m8n8.x4.trans.shared.b16 {%0,%1,%2,%3}, [%4];"
                 : "=r"(r[0]), "=r"(r[1]), "=r"(r[2]), "=r"(r[3]) : "r"(addr));
}
__device__ __forceinline__ void mma_fp16(float* d, const uint32_t* a, const uint32_t* b) {
    asm volatile(
        "mma.sync.aligned.m16n8k16.row.col.f32.f16.f16.f32 "
        "{%0,%1,%2,%3},{%4,%5,%6,%7},{%8,%9},{%0,%1,%2,%3};"
        : "+f"(d[0]), "+f"(d[1]), "+f"(d[2]), "+f"(d[3])
        : "r"(a[0]), "r"(a[1]), "r"(a[2]), "r"(a[3]), "r"(b[0]), "r"(b[1]));
}
__device__ __forceinline__ uint32_t smem_u32(const void* p) {
    uint32_t a;
    asm("{ .reg .u64 t; cvta.to.shared.u64 t, %1; cvt.u32.u64 %0, t; }" : "=r"(a) : "l"(p));
    return a;
}

// ------------------------------------------------------------------
// FP16 GEMM via mma.sync.m16n8k16 + ldmatrix.
// BM=128, BN template {64,128}, BK=32, 256 thr (8 warps 4x2).
// Grid: x = N blocks, y = M blocks, z = split-K.
// headStride != 0: B is per-head [H][K][64]; col -> head = col>>6.
// ------------------------------------------------------------------
template<int BN>
__global__ __launch_bounds__(256) void gemm16(
    const float* __restrict__ A, int lda,
    const float* __restrict__ B, int ldb, int headStride,
    float* __restrict__ C, int ldc,
    int kIters, int kChunk, long cSplit,
    const float* __restrict__ bias,
    const float* __restrict__ resid,
    int relu)
{
    constexpr int ABYTES = 128 * 64;
    constexpr int BBYTES = 32 * BN * 2;
    constexpr int NB  = (BN == 128) ? 2 : 1;     // B chunks per thread
    constexpr int BSH = (BN == 128) ? 4 : 3;     // id>>BSH = B row (k)
    constexpr int BMSK = BN / 8 - 1;
    constexpr int NTP = BN / 32;                 // ldsm_x4_t count per kk
    __shared__ char sm[2][ABYTES + BBYTES];

    const int tid = threadIdx.x;
    const int m0 = blockIdx.y * 128;
    const int n0 = blockIdx.x * BN;
    const int k0 = blockIdx.z * kChunk;
    const int warp = tid >> 5, lane = tid & 31;
    const int wm = warp >> 1, wn = warp & 1;
    const int gid = lane >> 2, tg = lane & 3;

    // staging assignments (fixed per thread)
    const float* aptr[2]; int asto[2];
#pragma unroll
    for (int i = 0; i < 2; i++) {
        int id = tid + i * 256, r = id >> 2, c = id & 3;
        aptr[i] = A + (long)(m0 + r) * lda + k0 + c * 8;
        asto[i] = aoff(r, c);
    }
    const int rowStr = headStride ? 64 : ldb;
    const float* bptr[NB]; int bsto[NB];
#pragma unroll
    for (int i = 0; i < NB; i++) {
        int id = tid + i * 256, k = id >> BSH, c = id & BMSK;
        int col = n0 + c * 8;
        const float* bb = headStride ? (B + (long)(col >> 6) * headStride + (col & 63))
                                     : (B + col);
        bptr[i] = bb + (long)(k0 + k) * rowStr;
        bsto[i] = ABYTES + boff<BN>(k, c);
    }

    const int aRowL = lane & 15, aChL = lane >> 4;
    uint32_t sbase[2] = { smem_u32(&sm[0][0]), smem_u32(&sm[1][0]) };

    float acc[2][BN / 16][4];
#pragma unroll
    for (int i = 0; i < 2; i++)
#pragma unroll
        for (int j = 0; j < BN / 16; j++)
#pragma unroll
            for (int l = 0; l < 4; l++) acc[i][j][l] = 0.f;

    float4 ra[2][2], rb[NB][2];

    // ---- prologue: stage tile 0
#pragma unroll
    for (int i = 0; i < 2; i++) {
        ra[i][0] = *(const float4*)(aptr[i]);
        ra[i][1] = *(const float4*)(aptr[i] + 4);
    }
#pragma unroll
    for (int i = 0; i < NB; i++) {
        rb[i][0] = *(const float4*)(bptr[i]);
        rb[i][1] = *(const float4*)(bptr[i] + 4);
    }
    {
        uint4 u;
#pragma unroll
        for (int i = 0; i < 2; i++) {
            u.x = pack2(ra[i][0].x, ra[i][0].y); u.y = pack2(ra[i][0].z, ra[i][0].w);
            u.z = pack2(ra[i][1].x, ra[i][1].y); u.w = pack2(ra[i][1].z, ra[i][1].w);
            *(uint4*)&sm[0][asto[i]] = u;
        }
#pragma unroll
        for (int i = 0; i < NB; i++) {
            u.x = pack2(rb[i][0].x, rb[i][0].y); u.y = pack2(rb[i][0].z, rb[i][0].w);
            u.z = pack2(rb[i][1].x, rb[i][1].y); u.w = pack2(rb[i][1].z, rb[i][1].w);
            *(uint4*)&sm[0][bsto[i]] = u;
        }
    }
    __syncthreads();

    for (int t = 0; t < kIters; t++) {
        if (t + 1 < kIters) {
            const long ka = (long)(t + 1) * 32;
            const long kbb = (long)(t + 1) * 32 * rowStr;
#pragma unroll
            for (int i = 0; i < 2; i++) {
                ra[i][0] = *(const float4*)(aptr[i] + ka);
                ra[i][1] = *(const float4*)(aptr[i] + ka + 4);
            }
#pragma unroll
            for (int i = 0; i < NB; i++) {
                rb[i][0] = *(const float4*)(bptr[i] + kbb);
                rb[i][1] = *(const float4*)(bptr[i] + kbb + 4);
            }
        }
        const uint32_t sa = sbase[t & 1];
        const uint32_t sbB = sbase[t & 1] + ABYTES;
#pragma unroll
        for (int kk = 0; kk < 2; kk++) {
            uint32_t af[2][4], bf[NTP][4];
#pragma unroll
            for (int mt = 0; mt < 2; mt++)
                ldsm_x4(af[mt], sa + aoff(wm * 32 + mt * 16 + aRowL, kk * 2 + aChL));
#pragma unroll
            for (int ntp = 0; ntp < NTP; ntp++)
                ldsm_x4_t(bf[ntp], sbB + boff<BN>(kk * 16 + aRowL,
                                                  wn * (BN / 16) + ntp * 2 + aChL));
#pragma unroll
            for (int mt = 0; mt < 2; mt++)
#pragma unroll
                for (int ntp = 0; ntp < NTP; ntp++) {
                    mma_fp16(acc[mt][ntp * 2 + 0], af[mt], &bf[ntp][0]);
                    mma_fp16(acc[mt][ntp * 2 + 1], af[mt], &bf[ntp][2]);
                }
        }
        if (t + 1 < kIters) {
            char* d = sm[(t + 1) & 1];
            uint4 u;
#pragma unroll
            for (int i = 0; i < 2; i++) {
                u.x = pack2(ra[i][0].x, ra[i][0].y); u.y = pack2(ra[i][0].z, ra[i][0].w);
                u.z = pack2(ra[i][1].x, ra[i][1].y); u.w = pack2(ra[i][1].z, ra[i][1].w);
                *(uint4*)&d[asto[i]] = u;
            }
#pragma unroll
            for (int i = 0; i < NB; i++) {
                u.x = pack2(rb[i][0].x, rb[i][0].y); u.y = pack2(rb[i][0].z, rb[i][0].w);
                u.z = pack2(rb[i][1].x, rb[i][1].y); u.w = pack2(rb[i][1].z, rb[i][1].w);
                *(uint4*)&d[bsto[i]] = u;
            }
            __syncthreads();
        }
    }

    // ---- epilogue
    float* Cp = C + (long)blockIdx.z * cSplit;
#pragma unroll
    for (int mt = 0; mt < 2; mt++) {
        int r0 = m0 + wm * 32 + mt * 16 + gid;
#pragma unroll
        for (int nt = 0; nt < BN / 16; nt++) {
            int col = n0 + wn * (BN / 2) + nt * 8 + tg * 2;
            float2 v0 = make_float2(acc[mt][nt][0], acc[mt][nt][1]);
            float2 v1 = make_float2(acc[mt][nt][2], acc[mt][nt][3]);
            if (bias) {
                float2 bv = *(const float2*)(bias + col);
                v0.x += bv.x; v0.y += bv.y; v1.x += bv.x; v1.y += bv.y;
            }
            if (resid) {
                float2 q0 = *(const float2*)(resid + (long)r0 * ldc + col);
                float2 q1 = *(const float2*)(resid + (long)(r0 + 8) * ldc + col);
                v0.x += q0.x; v0.y += q0.y; v1.x += q1.x; v1.y += q1.y;
            }
            if (relu) {
                v0.x = fmaxf(v0.x, 0.f); v0.y = fmaxf(v0.y, 0.f);
                v1.x = fmaxf(v1.x, 0.f); v1.y = fmaxf(v1.y, 0.f);
            }
            *(float2*)(Cp + (long)r0 * ldc + col) = v0;
            *(float2*)(Cp + (long)(r0 + 8) * ldc + col) = v1;
        }
    }
}

// ------------------------------------------------------------------
// Fused attention per (b,h): 64x64, fp32 SIMT, 256 threads (unchanged)
// ------------------------------------------------------------------
__global__ __launch_bounds__(256) void attn_k(
    const float* __restrict__ Q, const float* __restrict__ Kt,
    const float* __restrict__ V, float* __restrict__ Ctx)
{
    __shared__ float sA[64 * 68];
    __shared__ float sB[64 * 68];
    __shared__ float red[64];

    const int tid = threadIdx.x;
    const int b = blockIdx.x >> 3, h = blockIdx.x & 7;
    const long base = (long)b * 32768 + h * 64;

    for (int idx = tid; idx < 4096; idx += 256) {
        int s = idx >> 6, e = idx & 63;
        sA[s * 68 + e] = Q[base + (long)s * 512 + e];
        sB[s * 68 + e] = Kt[base + (long)s * 512 + e];
    }
    __syncthreads();

    const int ty = tid >> 4, tx = tid & 15;
    float sc[4][4] = {};
    for (int k = 0; k < 64; k += 4) {
        float4 qv[4], kv[4];
#pragma unroll
        for (int r = 0; r < 4; r++) qv[r] = *(const float4*)&sA[(4 * ty + r) * 68 + k];
#pragma unroll
        for (int c = 0; c < 4; c++) kv[c] = *(const float4*)&sB[(4 * tx + c) * 68 + k];
#pragma unroll
        for (int r = 0; r < 4; r++)
#pragma unroll
            for (int c = 0; c < 4; c++)
                sc[r][c] += qv[r].x * kv[c].x + qv[r].y * kv[c].y +
                            qv[r].z * kv[c].z + qv[r].w * kv[c].w;
    }
    __syncthreads();

#pragma unroll
    for (int r = 0; r < 4; r++)
        *(float4*)&sA[(4 * ty + r) * 68 + 4 * tx] =
            make_float4(sc[r][0] * 0.125f, sc[r][1] * 0.125f,
                        sc[r][2] * 0.125f, sc[r][3] * 0.125f);
    for (int idx = tid; idx < 4096; idx += 256) {
        int s = idx >> 6, e = idx & 63;
        sB[s * 68 + e] = V[base + (long)s * 512 + e];
    }
    __syncthreads();

    if (tid < 64) {
        float m = -1e30f;
        for (int j = 0; j < 64; j++) m = fmaxf(m, sA[tid * 68 + j]);
        float sum = 0.f;
        for (int j = 0; j < 64; j++) {
            float e = __expf(sA[tid * 68 + j] - m);
            sA[tid * 68 + j] = e; sum += e;
        }
        red[tid] = 1.f / sum;
    }
    __syncthreads();

    float ct[4][4] = {};
    for (int j = 0; j < 64; j++) {
        float4 vv = *(const float4*)&sB[j * 68 + 4 * tx];
#pragma unroll
        for (int r = 0; r < 4; r++) {
            float p = sA[(4 * ty + r) * 68 + j];
            ct[r][0] += p * vv.x; ct[r][1] += p * vv.y;
            ct[r][2] += p * vv.z; ct[r][3] += p * vv.w;
        }
    }
#pragma unroll
    for (int r = 0; r < 4; r++) {
        float rs = red[4 * ty + r];
        *(float4*)(Ctx + base + (long)(4 * ty + r) * 512 + 4 * tx) =
            make_float4(ct[r][0] * rs, ct[r][1] * rs, ct[r][2] * rs, ct[r][3] * rs);
    }
}

// ---------------- LayerNorm width=512, warp per row ----------------
__global__ __launch_bounds__(256) void ln512_k(
    const float* __restrict__ in, float* __restrict__ out,
    const float* __restrict__ gam, const float* __restrict__ bet)
{
    const int row = blockIdx.x * 8 + (threadIdx.x >> 5);
    const int lane = threadIdx.x & 31;
    const float* p = in + (long)row * 512;
    float v[16], s = 0.f, s2 = 0.f;
#pragma unroll
    for (int i = 0; i < 16; i++) {
        v[i] = p[lane + 32 * i]; s += v[i]; s2 = fmaf(v[i], v[i], s2);
    }
#pragma unroll
    for (int o = 16; o > 0; o >>= 1) {
        s += __shfl_xor_sync(~0u, s, o); s2 += __shfl_xor_sync(~0u, s2, o);
    }
    float mu = s * (1.f / 512.f);
    float rsg = rsqrtf(s2 * (1.f / 512.f) - mu * mu + 1e-5f);
    float* q = out + (long)row * 512;
#pragma unroll
    for (int i = 0; i < 16; i++) {
        int c = lane + 32 * i;
        q[c] = (v[i] - mu) * rsg * gam[c] + bet[c];
    }
}

// ---------------- LayerNorm width=32768, block per row ----------------
__global__ __launch_bounds__(1024) void ln32k_k(
    const float* __restrict__ in, float* __restrict__ out,
    const float* __restrict__ gam, const float* __restrict__ bet)
{
    __shared__ float rs1[32], rs2[32], stat[2];
    const int row = blockIdx.x;
    const float* p = in + (long)row * 32768;
    float s = 0.f, s2 = 0.f;
    for (int i = threadIdx.x; i < 32768; i += 1024) {
        float v = p[i]; s += v; s2 = fmaf(v, v, s2);
    }
#pragma unroll
    for (int o = 16; o > 0; o >>= 1) {
        s += __shfl_xor_sync(~0u, s, o); s2 += __shfl_xor_sync(~0u, s2, o);
    }
    if ((threadIdx.x & 31) == 0) { rs1[threadIdx.x >> 5] = s; rs2[threadIdx.x >> 5] = s2; }
    __syncthreads();
    if (threadIdx.x < 32) {
        s = rs1[threadIdx.x]; s2 = rs2[threadIdx.x];
#pragma unroll
        for (int o = 16; o > 0; o >>= 1) {
            s += __shfl_xor_sync(~0u, s, o); s2 += __shfl_xor_sync(~0u, s2, o);
        }
        if (threadIdx.x == 0) {
            float mu = s * (1.f / 32768.f);
            stat[0] = mu; stat[1] = rsqrtf(s2 * (1.f / 32768.f) - mu * mu + 1e-5f);
        }
    }
    __syncthreads();
    float mu = stat[0], rsg = stat[1];
    float* q = out + (long)row * 32768;
    for (int i = threadIdx.x; i < 32768; i += 1024)
        q[i] = (p[i] - mu) * rsg * gam[i] + bet[i];
}

// ---------------- split-K reducers (fixed order, deterministic) ----------------
__global__ void reduce16_relu_k(const float* __restrict__ part,
                                const float* __restrict__ b1,
                                float* __restrict__ out)
{
    int idx = blockIdx.x * blockDim.x + threadIdx.x;  // < 256*2048
    float s = 0.f;
#pragma unroll
    for (int z = 0; z < 16; z++) s += part[(long)z * 524288 + idx];
    s += b1[idx & 2047];
    out[idx] = fmaxf(s, 0.f);
}

__global__ void reduce_out_k(const float* __restrict__ part,
                             const float* __restrict__ bf,
                             float* __restrict__ out)
{
    int idx = blockIdx.x * blockDim.x + threadIdx.x;
    if (idx >= 12800) return;
    int m = idx / 50, j = idx % 50;
    float s = bf[j];
#pragma unroll
    for (int z = 0; z < 64; z++) s += part[(long)z * 16384 + m * 64 + j];
    out[idx] = s;
}

// ---------------- pad Wf [32768,50] -> [32768,64] ----------------
__global__ void pad_wf_k(const float* __restrict__ Wf, float* __restrict__ Wfp)
{
    int idx = blockIdx.x * blockDim.x + threadIdx.x;  // < 32768*64
    int k = idx >> 6, j = idx & 63;
    Wfp[idx] = (j < 50) ? Wf[k * 50 + j] : 0.f;
}

// ------------------------------------------------------------------
extern "C" void kernel_launch(void* const* d_in, const int* in_sizes, int n_in,
                              void* d_out, int out_size)
{
    const float* inputs = (const float*)d_in[0];
    const float* Wq = (const float*)d_in[1];  const float* bq = (const float*)d_in[2];
    const float* Wk = (const float*)d_in[3];  const float* bk = (const float*)d_in[4];
    const float* Wv = (const float*)d_in[5];  const float* bv = (const float*)d_in[6];
    const float* Wo = (const float*)d_in[7];  const float* bo = (const float*)d_in[8];
    const float* ln1g = (const float*)d_in[9];  const float* ln1b = (const float*)d_in[10];
    const float* W1 = (const float*)d_in[11]; const float* b1 = (const float*)d_in[12];
    const float* W2 = (const float*)d_in[13]; const float* b2 = (const float*)d_in[14];
    const float* ln2g = (const float*)d_in[15]; const float* ln2b = (const float*)d_in[16];
    const float* Wf = (const float*)d_in[17]; const float* bf = (const float*)d_in[18];
    float* out = (float*)d_out;

    float *q, *k, *v, *ctx, *res1, *x, *p4, *h, *v2, *y, *wfp, *p6;
    cudaGetSymbolAddress((void**)&q, g_q);
    cudaGetSymbolAddress((void**)&k, g_k);
    cudaGetSymbolAddress((void**)&v, g_v);
    cudaGetSymbolAddress((void**)&ctx, g_ctx);
    cudaGetSymbolAddress((void**)&res1, g_res1);
    cudaGetSymbolAddress((void**)&x, g_x);
    cudaGetSymbolAddress((void**)&p4, g_p4);
    cudaGetSymbolAddress((void**)&h, g_h);
    cudaGetSymbolAddress((void**)&v2, g_v2);
    cudaGetSymbolAddress((void**)&y, g_y);
    cudaGetSymbolAddress((void**)&wfp, g_wfp);
    cudaGetSymbolAddress((void**)&p6, g_p6);

    // Wf padding (independent)
    pad_wf_k<<<8192, 256>>>(Wf, wfp);

    // QKV projections: [16384,512] @ per-head [512,64] -> [16384, 512]
    gemm16<128><<<dim3(4, 128, 1), 256>>>(inputs, 512, Wq, 64, 32768,
                                          q, 512, 16, 0, 0, bq, nullptr, 0);
    gemm16<128><<<dim3(4, 128, 1), 256>>>(inputs, 512, Wk, 64, 32768,
                                          k, 512, 16, 0, 0, bk, nullptr, 0);
    gemm16<128><<<dim3(4, 128, 1), 256>>>(inputs, 512, Wv, 64, 32768,
                                          v, 512, 16, 0, 0, bv, nullptr, 0);

    // attention per (b,h)
    attn_k<<<2048, 256>>>(q, k, v, ctx);

    // output projection + bias + residual(inputs)
    gemm16<128><<<dim3(4, 128, 1), 256>>>(ctx, 512, Wo, 512, 0,
                                          res1, 512, 16, 0, 0, bo, inputs, 0);

    // LN1 -> x (viewed as [256, 32768])
    ln512_k<<<2048, 256>>>(res1, x, ln1g, ln1b);

    // h = relu(x @ W1 + b1): M=256,N=2048,K=32768, split-K 16
    gemm16<128><<<dim3(16, 2, 16), 256>>>(x, 32768, W1, 2048, 0,
                                          p4, 2048, 64, 2048, 524288,
                                          nullptr, nullptr, 0);
    reduce16_relu_k<<<2048, 256>>>(p4, b1, h);

    // v2 = h @ W2 + b2 + x: M=256,N=32768,K=2048
    gemm16<128><<<dim3(256, 2, 1), 256>>>(h, 2048, W2, 32768, 0,
                                          v2, 32768, 64, 0, 0, b2, x, 0);

    // LN2 -> y
    ln32k_k<<<256, 1024>>>(v2, y, ln2g, ln2b);

    // logits partials: y @ wfp: M=256,N=64,K=32768, split-K 64
    gemm16<64><<<dim3(1, 2, 64), 256>>>(y, 32768, wfp, 64, 0,
                                        p6, 64, 16, 512, 16384,
                                        nullptr, nullptr, 0);
    reduce_out_k<<<50, 256>>>(p6, bf, out);
}

// round 11
// speedup vs baseline: 2.6247x; 1.2994x over previous
#include <cuda_runtime.h>
#include <cuda_fp16.h>
#include <cstdint>

// B=256, S=64, D=512, H=8, DK=DV=64, DFF=2048, IN=32768, OUT=50

// ---------------- device scratch (static, no allocation) ----------------
__device__ __half g_inh [16384L*512];
__device__ __half g_qh  [16384L*512];
__device__ __half g_kh  [16384L*512];
__device__ __half g_vh  [16384L*512];
__device__ __half g_ctxh[16384L*512];
__device__ __half g_xh  [256L*32768];
__device__ __half g_hh  [256L*2048];
__device__ __half g_yh  [256L*32768];
__device__ float  g_res1[16384L*512];
__device__ float  g_x   [16384L*512];
__device__ float  g_p4  [16L*256*2048];
__device__ float  g_v2  [256L*32768];
__device__ float  g_wfp [32768L*64];
__device__ float  g_p6  [64L*256*64];

// ---------------- helpers ----------------
__device__ __forceinline__ uint32_t pack2(float a, float b) {
    __half2 h = __floats2half2_rn(a, b);
    return *reinterpret_cast<uint32_t*>(&h);
}
// A smem: 128 rows x 32 halves (64B/row), 2 rows per 128B atom, XOR swizzle.
__device__ __forceinline__ int aoff(int r, int c) {   // c = 16B chunk 0..3
    return ((r >> 1) << 7) + (((((r & 1) << 2) + c) ^ ((r >> 1) & 7)) << 4);
}
// B smem: 32 rows x BN halves, XOR swizzle on low 3 chunk bits.
template<int BN>
__device__ __forceinline__ int boff(int k, int c) {
    return k * (2 * BN) + ((((c & ~7) | ((c ^ (k & 7)) & 7))) << 4);
}
// full-128B-row swizzle (attention tiles: 64 halves = 128B rows)
__device__ __forceinline__ int foff(int r, int c) {   // c = 16B chunk 0..7
    return (r << 7) + (((c ^ (r & 7)) & 7) << 4);
}
__device__ __forceinline__ void ldsm_x4(uint32_t* r, uint32_t addr) {
    asm volatile("ldmatrix.sync.aligned.m8n8.x4.shared.b16 {%0,%1,%2,%3}, [%4];"
                 : "=r"(r[0]), "=r"(r[1]), "=r"(r[2]), "=r"(r[3]) : "r"(addr));
}
__device__ __forceinline__ void ldsm_x4_t(uint32_t* r, uint32_t addr) {
    asm volatile("ldmatrix.sync.aligned.m8n8.x4.trans.shared.b16 {%0,%1,%2,%3}, [%4];"
                 : "=r"(r[0]), "=r"(r[1]), "=r"(r[2]), "=r"(r[3]) : "r"(addr));
}
__device__ __forceinline__ void mma_fp16(float* d, const uint32_t* a, const uint32_t* b) {
    asm volatile(
        "mma.sync.aligned.m16n8k16.row.col.f32.f16.f16.f32 "
        "{%0,%1,%2,%3},{%4,%5,%6,%7},{%8,%9},{%0,%1,%2,%3};"
        : "+f"(d[0]), "+f"(d[1]), "+f"(d[2]), "+f"(d[3])
        : "r"(a[0]), "r"(a[1]), "r"(a[2]), "r"(a[3]), "r"(b[0]), "r"(b[1]));
}
__device__ __forceinline__ void mma_fp16_2(float* d, const uint32_t* a, uint32_t b0, uint32_t b1) {
    asm volatile(
        "mma.sync.aligned.m16n8k16.row.col.f32.f16.f16.f32 "
        "{%0,%1,%2,%3},{%4,%5,%6,%7},{%8,%9},{%0,%1,%2,%3};"
        : "+f"(d[0]), "+f"(d[1]), "+f"(d[2]), "+f"(d[3])
        : "r"(a[0]), "r"(a[1]), "r"(a[2]), "r"(a[3]), "r"(b0), "r"(b1));
}
__device__ __forceinline__ uint32_t smem_u32(const void* p) {
    uint32_t a;
    asm("{ .reg .u64 t; cvta.to.shared.u64 t, %1; cvt.u32.u64 %0, t; }" : "=r"(a) : "l"(p));
    return a;
}

// ------------------------------------------------------------------
// FP16 GEMM: A fp16 [*,lda], B fp32 (converted in staging), fp32 acc.
// BM=128, BN {64,128}, BK=32, 256 thr. Grid: x=N, y=M, z=splitK.
// OH: write __half output, else float (+bias/resid/relu).
// ------------------------------------------------------------------
template<int BN, bool OH>
__global__ __launch_bounds__(256) void gemm16(
    const __half* __restrict__ A, int lda,
    const float* __restrict__ B, int ldb, int headStride,
    void* __restrict__ Cv, int ldc,
    int kIters, int kChunk, long cSplit,
    const float* __restrict__ bias,
    const float* __restrict__ resid,
    int relu)
{
    constexpr int ABYTES = 128 * 64;
    constexpr int BBYTES = 32 * BN * 2;
    constexpr int NB  = (BN == 128) ? 2 : 1;
    constexpr int BSH = (BN == 128) ? 4 : 3;
    constexpr int BMSK = BN / 8 - 1;
    constexpr int NTP = BN / 32;
    __shared__ char sm[2][ABYTES + BBYTES];

    const int tid = threadIdx.x;
    const int m0 = blockIdx.y * 128;
    const int n0 = blockIdx.x * BN;
    const int k0 = blockIdx.z * kChunk;
    const int warp = tid >> 5, lane = tid & 31;
    const int wm = warp >> 1, wn = warp & 1;
    const int gid = lane >> 2, tg = lane & 3;

    // staging assignments
    const __half* aptr[2]; int asto[2];
#pragma unroll
    for (int i = 0; i < 2; i++) {
        int id = tid + i * 256, r = id >> 2, c = id & 3;
        aptr[i] = A + (long)(m0 + r) * lda + k0 + c * 8;
        asto[i] = aoff(r, c);
    }
    const int rowStr = headStride ? 64 : ldb;
    const float* bptr[NB]; int bsto[NB];
#pragma unroll
    for (int i = 0; i < NB; i++) {
        int id = tid + i * 256, k = id >> BSH, c = id & BMSK;
        int col = n0 + c * 8;
        const float* bb = headStride ? (B + (long)(col >> 6) * headStride + (col & 63))
                                     : (B + col);
        bptr[i] = bb + (long)(k0 + k) * rowStr;
        bsto[i] = ABYTES + boff<BN>(k, c);
    }

    const int aRowL = lane & 15, aChL = lane >> 4;
    uint32_t sbase[2] = { smem_u32(&sm[0][0]), smem_u32(&sm[1][0]) };

    float acc[2][BN / 16][4];
#pragma unroll
    for (int i = 0; i < 2; i++)
#pragma unroll
        for (int j = 0; j < BN / 16; j++)
#pragma unroll
            for (int l = 0; l < 4; l++) acc[i][j][l] = 0.f;

    uint4 rau[2]; float4 rb[NB][2];

    // prologue: stage tile 0
#pragma unroll
    for (int i = 0; i < 2; i++) rau[i] = *(const uint4*)(aptr[i]);
#pragma unroll
    for (int i = 0; i < NB; i++) {
        rb[i][0] = *(const float4*)(bptr[i]);
        rb[i][1] = *(const float4*)(bptr[i] + 4);
    }
#pragma unroll
    for (int i = 0; i < 2; i++) *(uint4*)&sm[0][asto[i]] = rau[i];
#pragma unroll
    for (int i = 0; i < NB; i++) {
        uint4 u;
        u.x = pack2(rb[i][0].x, rb[i][0].y); u.y = pack2(rb[i][0].z, rb[i][0].w);
        u.z = pack2(rb[i][1].x, rb[i][1].y); u.w = pack2(rb[i][1].z, rb[i][1].w);
        *(uint4*)&sm[0][bsto[i]] = u;
    }
    __syncthreads();

    for (int t = 0; t < kIters; t++) {
        if (t + 1 < kIters) {
            const long ka = (long)(t + 1) * 32;
            const long kbb = (long)(t + 1) * 32 * rowStr;
#pragma unroll
            for (int i = 0; i < 2; i++) rau[i] = *(const uint4*)(aptr[i] + ka);
#pragma unroll
            for (int i = 0; i < NB; i++) {
                rb[i][0] = *(const float4*)(bptr[i] + kbb);
                rb[i][1] = *(const float4*)(bptr[i] + kbb + 4);
            }
        }
        const uint32_t sa = sbase[t & 1];
        const uint32_t sbB = sbase[t & 1] + ABYTES;
#pragma unroll
        for (int kk = 0; kk < 2; kk++) {
            uint32_t af[2][4], bf[NTP][4];
#pragma unroll
            for (int mt = 0; mt < 2; mt++)
                ldsm_x4(af[mt], sa + aoff(wm * 32 + mt * 16 + aRowL, kk * 2 + aChL));
#pragma unroll
            for (int ntp = 0; ntp < NTP; ntp++)
                ldsm_x4_t(bf[ntp], sbB + boff<BN>(kk * 16 + aRowL,
                                                  wn * (BN / 16) + ntp * 2 + aChL));
#pragma unroll
            for (int mt = 0; mt < 2; mt++)
#pragma unroll
                for (int ntp = 0; ntp < NTP; ntp++) {
                    mma_fp16(acc[mt][ntp * 2 + 0], af[mt], &bf[ntp][0]);
                    mma_fp16(acc[mt][ntp * 2 + 1], af[mt], &bf[ntp][2]);
                }
        }
        if (t + 1 < kIters) {
            char* d = sm[(t + 1) & 1];
#pragma unroll
            for (int i = 0; i < 2; i++) *(uint4*)&d[asto[i]] = rau[i];
#pragma unroll
            for (int i = 0; i < NB; i++) {
                uint4 u;
                u.x = pack2(rb[i][0].x, rb[i][0].y); u.y = pack2(rb[i][0].z, rb[i][0].w);
                u.z = pack2(rb[i][1].x, rb[i][1].y); u.w = pack2(rb[i][1].z, rb[i][1].w);
                *(uint4*)&d[bsto[i]] = u;
            }
            __syncthreads();
        }
    }

    // epilogue
#pragma unroll
    for (int mt = 0; mt < 2; mt++) {
        int r0 = m0 + wm * 32 + mt * 16 + gid;
#pragma unroll
        for (int nt = 0; nt < BN / 16; nt++) {
            int col = n0 + wn * (BN / 2) + nt * 8 + tg * 2;
            float2 v0 = make_float2(acc[mt][nt][0], acc[mt][nt][1]);
            float2 v1 = make_float2(acc[mt][nt][2], acc[mt][nt][3]);
            if (bias) {
                float2 bv = *(const float2*)(bias + col);
                v0.x += bv.x; v0.y += bv.y; v1.x += bv.x; v1.y += bv.y;
            }
            if (OH) {
                __half* Ch = (__half*)Cv;
                *(__half2*)(Ch + (long)r0 * ldc + col) = __floats2half2_rn(v0.x, v0.y);
                *(__half2*)(Ch + (long)(r0 + 8) * ldc + col) = __floats2half2_rn(v1.x, v1.y);
            } else {
                float* Cp = (float*)Cv + (long)blockIdx.z * cSplit;
                if (resid) {
                    float2 q0 = *(const float2*)(resid + (long)r0 * ldc + col);
                    float2 q1 = *(const float2*)(resid + (long)(r0 + 8) * ldc + col);
                    v0.x += q0.x; v0.y += q0.y; v1.x += q1.x; v1.y += q1.y;
                }
                if (relu) {
                    v0.x = fmaxf(v0.x, 0.f); v0.y = fmaxf(v0.y, 0.f);
                    v1.x = fmaxf(v1.x, 0.f); v1.y = fmaxf(v1.y, 0.f);
                }
                *(float2*)(Cp + (long)r0 * ldc + col) = v0;
                *(float2*)(Cp + (long)(r0 + 8) * ldc + col) = v1;
            }
        }
    }
}

// ------------------------------------------------------------------
// MMA attention per (b,h): 128 threads (4 warps), fp16 in/out, fp32 acc.
// ------------------------------------------------------------------
__global__ __launch_bounds__(128) void attn_mma(
    const __half* __restrict__ Qh, const __half* __restrict__ Kh,
    const __half* __restrict__ Vh, __half* __restrict__ Ctx)
{
    __shared__ __align__(16) char sq[64 * 128], sk[64 * 128], sv[64 * 128];
    const int tid = threadIdx.x;
    const int w = tid >> 5, lane = tid & 31;
    const int gid = lane >> 2, tg = lane & 3;
    const int b = blockIdx.x >> 3, h = blockIdx.x & 7;
    const long base = (long)(b * 64) * 512 + h * 64;

    // stage Q/K/V: 64 rows x 8 16B-chunks each
#pragma unroll
    for (int i = 0; i < 4; i++) {
        int id = tid + i * 128, r = id >> 3, c = id & 7;
        int so = foff(r, c);
        const long go = base + (long)r * 512 + c * 8;
        *(uint4*)(sq + so) = *(const uint4*)(Qh + go);
        *(uint4*)(sk + so) = *(const uint4*)(Kh + go);
        *(uint4*)(sv + so) = *(const uint4*)(Vh + go);
    }
    __syncthreads();

    const uint32_t sqb = smem_u32(sq), skb = smem_u32(sk), svb = smem_u32(sv);
    const int rowL = lane & 15, chL = lane >> 4;

    // S = Q @ K^T : warp rows w*16..+15, all 64 cols
    float sacc[8][4];
#pragma unroll
    for (int j = 0; j < 8; j++)
#pragma unroll
        for (int l = 0; l < 4; l++) sacc[j][l] = 0.f;
#pragma unroll
    for (int kk = 0; kk < 4; kk++) {
        uint32_t a[4];
        ldsm_x4(a, sqb + foff(w * 16 + rowL, kk * 2 + chL));
#pragma unroll
        for (int g = 0; g < 4; g++) {
            uint32_t bk[4];
            ldsm_x4(bk, skb + foff(g * 16 + rowL, kk * 2 + chL));
            mma_fp16_2(sacc[g * 2 + 0], a, bk[0], bk[2]);
            mma_fp16_2(sacc[g * 2 + 1], a, bk[1], bk[3]);
        }
    }

    // softmax over rows (thread owns rows gid, gid+8; cols 8nt x {tg*2,+1})
    float mx0 = -1e30f, mx1 = -1e30f;
#pragma unroll
    for (int j = 0; j < 8; j++) {
#pragma unroll
        for (int l = 0; l < 4; l++) sacc[j][l] *= 0.125f;
        mx0 = fmaxf(mx0, fmaxf(sacc[j][0], sacc[j][1]));
        mx1 = fmaxf(mx1, fmaxf(sacc[j][2], sacc[j][3]));
    }
#pragma unroll
    for (int o = 1; o < 4; o <<= 1) {
        mx0 = fmaxf(mx0, __shfl_xor_sync(~0u, mx0, o));
        mx1 = fmaxf(mx1, __shfl_xor_sync(~0u, mx1, o));
    }
    float s0 = 0.f, s1 = 0.f;
#pragma unroll
    for (int j = 0; j < 8; j++) {
        sacc[j][0] = __expf(sacc[j][0] - mx0);
        sacc[j][1] = __expf(sacc[j][1] - mx0);
        sacc[j][2] = __expf(sacc[j][2] - mx1);
        sacc[j][3] = __expf(sacc[j][3] - mx1);
        s0 += sacc[j][0] + sacc[j][1];
        s1 += sacc[j][2] + sacc[j][3];
    }
#pragma unroll
    for (int o = 1; o < 4; o <<= 1) {
        s0 += __shfl_xor_sync(~0u, s0, o);
        s1 += __shfl_xor_sync(~0u, s1, o);
    }
    const float r0 = 1.f / s0, r1 = 1.f / s1;

    // P fragments directly from registers: A k-chunk kk <- acc nt {2kk, 2kk+1}
    uint32_t ap[4][4];
#pragma unroll
    for (int kk = 0; kk < 4; kk++) {
        ap[kk][0] = pack2(sacc[kk * 2][0], sacc[kk * 2][1]);
        ap[kk][1] = pack2(sacc[kk * 2][2], sacc[kk * 2][3]);
        ap[kk][2] = pack2(sacc[kk * 2 + 1][0], sacc[kk * 2 + 1][1]);
        ap[kk][3] = pack2(sacc[kk * 2 + 1][2], sacc[kk * 2 + 1][3]);
    }

    // ctx = P @ V
    float cacc[8][4];
#pragma unroll
    for (int j = 0; j < 8; j++)
#pragma unroll
        for (int l = 0; l < 4; l++) cacc[j][l] = 0.f;
#pragma unroll
    for (int kk = 0; kk < 4; kk++) {
#pragma unroll
        for (int g = 0; g < 4; g++) {
            uint32_t bv[4];
            ldsm_x4_t(bv, svb + foff(kk * 16 + rowL, g * 2 + chL));
            mma_fp16_2(cacc[g * 2 + 0], ap[kk], bv[0], bv[1]);
            mma_fp16_2(cacc[g * 2 + 1], ap[kk], bv[2], bv[3]);
        }
    }

    // normalize + write fp16
    const long orow0 = (long)(b * 64 + w * 16 + gid) * 512 + h * 64;
    const long orow1 = orow0 + 8 * 512;
#pragma unroll
    for (int nt = 0; nt < 8; nt++) {
        int col = nt * 8 + tg * 2;
        *(__half2*)(Ctx + orow0 + col) = __floats2half2_rn(cacc[nt][0] * r0, cacc[nt][1] * r0);
        *(__half2*)(Ctx + orow1 + col) = __floats2half2_rn(cacc[nt][2] * r1, cacc[nt][3] * r1);
    }
}

// ---------------- fp32 -> fp16 bulk convert ----------------
__global__ void cvt_f2h(const float* __restrict__ in, __half* __restrict__ out)
{
    int idx = blockIdx.x * 256 + threadIdx.x;
    float4 f = ((const float4*)in)[idx];
    __half2* o = (__half2*)out + idx * 2;
    o[0] = __floats2half2_rn(f.x, f.y);
    o[1] = __floats2half2_rn(f.z, f.w);
}

// ---------------- LayerNorm width=512, dual fp32+fp16 out ----------------
__global__ __launch_bounds__(256) void ln512_dual(
    const float* __restrict__ in, float* __restrict__ out, __half* __restrict__ outh,
    const float* __restrict__ gam, const float* __restrict__ bet)
{
    const int row = blockIdx.x * 8 + (threadIdx.x >> 5);
    const int lane = threadIdx.x & 31;
    const float* p = in + (long)row * 512;
    float v[16], s = 0.f, s2 = 0.f;
#pragma unroll
    for (int i = 0; i < 16; i++) {
        v[i] = p[lane + 32 * i]; s += v[i]; s2 = fmaf(v[i], v[i], s2);
    }
#pragma unroll
    for (int o = 16; o > 0; o >>= 1) {
        s += __shfl_xor_sync(~0u, s, o); s2 += __shfl_xor_sync(~0u, s2, o);
    }
    float mu = s * (1.f / 512.f);
    float rsg = rsqrtf(s2 * (1.f / 512.f) - mu * mu + 1e-5f);
    float* q = out + (long)row * 512;
    __half* qh = outh + (long)row * 512;
#pragma unroll
    for (int i = 0; i < 16; i++) {
        int c = lane + 32 * i;
        float r = (v[i] - mu) * rsg * gam[c] + bet[c];
        q[c] = r;
        qh[c] = __float2half_rn(r);
    }
}

// ---------------- LayerNorm width=32768, fp16 out ----------------
__global__ __launch_bounds__(1024) void ln32k_h(
    const float* __restrict__ in, __half* __restrict__ out,
    const float* __restrict__ gam, const float* __restrict__ bet)
{
    __shared__ float rs1[32], rs2[32], stat[2];
    const int row = blockIdx.x;
    const float* p = in + (long)row * 32768;
    float s = 0.f, s2 = 0.f;
    for (int i = threadIdx.x; i < 32768; i += 1024) {
        float v = p[i]; s += v; s2 = fmaf(v, v, s2);
    }
#pragma unroll
    for (int o = 16; o > 0; o >>= 1) {
        s += __shfl_xor_sync(~0u, s, o); s2 += __shfl_xor_sync(~0u, s2, o);
    }
    if ((threadIdx.x & 31) == 0) { rs1[threadIdx.x >> 5] = s; rs2[threadIdx.x >> 5] = s2; }
    __syncthreads();
    if (threadIdx.x < 32) {
        s = rs1[threadIdx.x]; s2 = rs2[threadIdx.x];
#pragma unroll
        for (int o = 16; o > 0; o >>= 1) {
            s += __shfl_xor_sync(~0u, s, o); s2 += __shfl_xor_sync(~0u, s2, o);
        }
        if (threadIdx.x == 0) {
            float mu = s * (1.f / 32768.f);
            stat[0] = mu; stat[1] = rsqrtf(s2 * (1.f / 32768.f) - mu * mu + 1e-5f);
        }
    }
    __syncthreads();
    float mu = stat[0], rsg = stat[1];
    __half* q = out + (long)row * 32768;
    for (int i = threadIdx.x; i < 32768; i += 1024)
        q[i] = __float2half_rn((p[i] - mu) * rsg * gam[i] + bet[i]);
}

// ---------------- reducers ----------------
__global__ void reduce16_relu_h(const float* __restrict__ part,
                                const float* __restrict__ b1, __half* __restrict__ out)
{
    int idx = blockIdx.x * 256 + threadIdx.x;  // < 524288
    float s = 0.f;
#pragma unroll
    for (int z = 0; z < 16; z++) s += part[(long)z * 524288 + idx];
    s += b1[idx & 2047];
    out[idx] = __float2half_rn(fmaxf(s, 0.f));
}

__global__ void reduce_out_k(const float* __restrict__ part,
                             const float* __restrict__ bf, float* __restrict__ out)
{
    int idx = blockIdx.x * 256 + threadIdx.x;
    if (idx >= 12800) return;
    int m = idx / 50, j = idx % 50;
    float s = bf[j];
#pragma unroll
    for (int z = 0; z < 64; z++) s += part[(long)z * 16384 + m * 64 + j];
    out[idx] = s;
}

__global__ void pad_wf_k(const float* __restrict__ Wf, float* __restrict__ Wfp)
{
    int idx = blockIdx.x * 256 + threadIdx.x;  // < 32768*64
    int k = idx >> 6, j = idx & 63;
    Wfp[idx] = (j < 50) ? Wf[k * 50 + j] : 0.f;
}

// ------------------------------------------------------------------
extern "C" void kernel_launch(void* const* d_in, const int* in_sizes, int n_in,
                              void* d_out, int out_size)
{
    const float* inputs = (const float*)d_in[0];
    const float* Wq = (const float*)d_in[1];  const float* bq = (const float*)d_in[2];
    const float* Wk = (const float*)d_in[3];  const float* bk = (const float*)d_in[4];
    const float* Wv = (const float*)d_in[5];  const float* bv = (const float*)d_in[6];
    const float* Wo = (const float*)d_in[7];  const float* bo = (const float*)d_in[8];
    const float* ln1g = (const float*)d_in[9];  const float* ln1b = (const float*)d_in[10];
    const float* W1 = (const float*)d_in[11]; const float* b1 = (const float*)d_in[12];
    const float* W2 = (const float*)d_in[13]; const float* b2 = (const float*)d_in[14];
    const float* ln2g = (const float*)d_in[15]; const float* ln2b = (const float*)d_in[16];
    const float* Wf = (const float*)d_in[17]; const float* bf = (const float*)d_in[18];
    float* out = (float*)d_out;

    __half *inh, *qh, *kh, *vh, *ctxh, *xh, *hh, *yh;
    float *res1, *x, *p4, *v2, *wfp, *p6;
    cudaGetSymbolAddress((void**)&inh, g_inh);
    cudaGetSymbolAddress((void**)&qh, g_qh);
    cudaGetSymbolAddress((void**)&kh, g_kh);
    cudaGetSymbolAddress((void**)&vh, g_vh);
    cudaGetSymbolAddress((void**)&ctxh, g_ctxh);
    cudaGetSymbolAddress((void**)&xh, g_xh);
    cudaGetSymbolAddress((void**)&hh, g_hh);
    cudaGetSymbolAddress((void**)&yh, g_yh);
    cudaGetSymbolAddress((void**)&res1, g_res1);
    cudaGetSymbolAddress((void**)&x, g_x);
    cudaGetSymbolAddress((void**)&p4, g_p4);
    cudaGetSymbolAddress((void**)&v2, g_v2);
    cudaGetSymbolAddress((void**)&wfp, g_wfp);
    cudaGetSymbolAddress((void**)&p6, g_p6);

    // independent prep
    pad_wf_k<<<8192, 256>>>(Wf, wfp);
    cvt_f2h<<<8192, 256>>>(inputs, inh);   // 16384*512 / 4 / 256 = 8192

    // QKV projections -> fp16 outputs
    gemm16<128, true><<<dim3(4, 128, 1), 256>>>(inh, 512, Wq, 64, 32768,
                                                qh, 512, 16, 0, 0, bq, nullptr, 0);
    gemm16<128, true><<<dim3(4, 128, 1), 256>>>(inh, 512, Wk, 64, 32768,
                                                kh, 512, 16, 0, 0, bk, nullptr, 0);
    gemm16<128, true><<<dim3(4, 128, 1), 256>>>(inh, 512, Wv, 64, 32768,
                                                vh, 512, 16, 0, 0, bv, nullptr, 0);

    // MMA attention
    attn_mma<<<2048, 128>>>(qh, kh, vh, ctxh);

    // output projection + bias + residual(inputs) -> fp32
    gemm16<128, false><<<dim3(4, 128, 1), 256>>>(ctxh, 512, Wo, 512, 0,
                                                 res1, 512, 16, 0, 0, bo, inputs, 0);

    // LN1 -> x (fp32) + xh (fp16)
    ln512_dual<<<2048, 256>>>(res1, x, xh, ln1g, ln1b);

    // h = relu(x @ W1 + b1): split-K 16 -> p4, reduce -> hh fp16
    gemm16<128, false><<<dim3(16, 2, 16), 256>>>(xh, 32768, W1, 2048, 0,
                                                 p4, 2048, 64, 2048, 524288,
                                                 nullptr, nullptr, 0);
    reduce16_relu_h<<<2048, 256>>>(p4, b1, hh);

    // v2 = h @ W2 + b2 + x -> fp32
    gemm16<128, false><<<dim3(256, 2, 1), 256>>>(hh, 2048, W2, 32768, 0,
                                                 v2, 32768, 64, 0, 0, b2, x, 0);

    // LN2 -> yh fp16
    ln32k_h<<<256, 1024>>>(v2, yh, ln2g, ln2b);

    // logits: y @ wfp split-K 64 -> p6, reduce -> out
    gemm16<64, false><<<dim3(1, 2, 64), 256>>>(yh, 32768, wfp, 64, 0,
                                               p6, 64, 16, 512, 16384,
                                               nullptr, nullptr, 0);
    reduce_out_k<<<50, 256>>>(p6, bf, out);
}

// round 12
// speedup vs baseline: 2.6733x; 1.0185x over previous
#include <cuda_runtime.h>
#include <cuda_fp16.h>
#include <cstdint>

// B=256, S=64, D=512, H=8, DK=DV=64, DFF=2048, IN=32768, OUT=50

// ---------------- device scratch (static, no allocation) ----------------
__device__ __half g_inh [16384L*512];
__device__ __half g_qh  [16384L*512];
__device__ __half g_kh  [16384L*512];
__device__ __half g_vh  [16384L*512];
__device__ __half g_ctxh[16384L*512];
__device__ __half g_xh  [256L*32768];
__device__ __half g_hh  [256L*2048];
__device__ __half g_yh  [256L*32768];
__device__ float  g_res1[16384L*512];
__device__ float  g_x   [16384L*512];
__device__ float  g_p4  [16L*256*2048];
__device__ float  g_v2  [256L*32768];
__device__ float  g_wfp [32768L*64];
__device__ float  g_p6  [64L*256*64];

// ---------------- helpers ----------------
__device__ __forceinline__ uint32_t pack2(float a, float b) {
    __half2 h = __floats2half2_rn(a, b);
    return *reinterpret_cast<uint32_t*>(&h);
}
// A smem: rows x 32 halves (64B/row), 2 rows per 128B atom, XOR swizzle.
__device__ __forceinline__ int aoff(int r, int c) {   // c = 16B chunk 0..3
    return ((r >> 1) << 7) + (((((r & 1) << 2) + c) ^ ((r >> 1) & 7)) << 4);
}
// B smem: 32 rows x BN halves, XOR swizzle on low 3 chunk bits.
template<int BN>
__device__ __forceinline__ int boff(int k, int c) {
    return k * (2 * BN) + ((((c & ~7) | ((c ^ (k & 7)) & 7))) << 4);
}
// full-128B-row swizzle (attention tiles: 64 halves = 128B rows)
__device__ __forceinline__ int foff(int r, int c) {   // c = 16B chunk 0..7
    return (r << 7) + (((c ^ (r & 7)) & 7) << 4);
}
__device__ __forceinline__ void ldsm_x4(uint32_t* r, uint32_t addr) {
    asm volatile("ldmatrix.sync.aligned.m8n8.x4.shared.b16 {%0,%1,%2,%3}, [%4];"
                 : "=r"(r[0]), "=r"(r[1]), "=r"(r[2]), "=r"(r[3]) : "r"(addr));
}
__device__ __forceinline__ void ldsm_x4_t(uint32_t* r, uint32_t addr) {
    asm volatile("ldmatrix.sync.aligned.m8n8.x4.trans.shared.b16 {%0,%1,%2,%3}, [%4];"
                 : "=r"(r[0]), "=r"(r[1]), "=r"(r[2]), "=r"(r[3]) : "r"(addr));
}
__device__ __forceinline__ void mma_fp16(float* d, const uint32_t* a, const uint32_t* b) {
    asm volatile(
        "mma.sync.aligned.m16n8k16.row.col.f32.f16.f16.f32 "
        "{%0,%1,%2,%3},{%4,%5,%6,%7},{%8,%9},{%0,%1,%2,%3};"
        : "+f"(d[0]), "+f"(d[1]), "+f"(d[2]), "+f"(d[3])
        : "r"(a[0]), "r"(a[1]), "r"(a[2]), "r"(a[3]), "r"(b[0]), "r"(b[1]));
}
__device__ __forceinline__ void mma_fp16_2(float* d, const uint32_t* a, uint32_t b0, uint32_t b1) {
    asm volatile(
        "mma.sync.aligned.m16n8k16.row.col.f32.f16.f16.f32 "
        "{%0,%1,%2,%3},{%4,%5,%6,%7},{%8,%9},{%0,%1,%2,%3};"
        : "+f"(d[0]), "+f"(d[1]), "+f"(d[2]), "+f"(d[3])
        : "r"(a[0]), "r"(a[1]), "r"(a[2]), "r"(a[3]), "r"(b0), "r"(b1));
}
__device__ __forceinline__ uint32_t smem_u32(const void* p) {
    uint32_t a;
    asm("{ .reg .u64 t; cvta.to.shared.u64 t, %1; cvt.u32.u64 %0, t; }" : "=r"(a) : "l"(p));
    return a;
}

// ------------------------------------------------------------------
// BIG fp16 GEMM: BM=256, BN=128, BK=32, 512 thr (16 warps, 4x4).
// A fp16 [*,lda]; B fp32 converted in staging. Grid: x=N, y=M, z=splitK.
// OH: __half output (+bias), else float (+bias/resid/relu).
// ------------------------------------------------------------------
template<bool OH>
__global__ __launch_bounds__(512) void gemm512(
    const __half* __restrict__ A, int lda,
    const float* __restrict__ B, int ldb, int headStride,
    void* __restrict__ Cv, int ldc,
    int kIters, int kChunk, long cSplit,
    const float* __restrict__ bias,
    const float* __restrict__ resid,
    int relu)
{
    constexpr int ABYTES = 256 * 64;   // 16384
    constexpr int BBYTES = 32 * 256;   // 8192
    __shared__ char sm[2][ABYTES + BBYTES];   // 48 KB

    const int tid = threadIdx.x;
    const int m0 = blockIdx.y * 256;
    const int n0 = blockIdx.x * 128;
    const int k0 = blockIdx.z * kChunk;
    const int warp = tid >> 5, lane = tid & 31;
    const int wm = warp >> 2, wn = warp & 3;          // 4x4
    const int gid = lane >> 2, tg = lane & 3;

    // staging assignments
    const __half* aptr[2]; int asto[2];
#pragma unroll
    for (int i = 0; i < 2; i++) {
        int id = tid + i * 512, r = id >> 2, c = id & 3;   // 1024 items
        aptr[i] = A + (long)(m0 + r) * lda + k0 + c * 8;
        asto[i] = aoff(r, c);
    }
    const int rowStr = headStride ? 64 : ldb;
    const float* bptr; int bsto;
    {
        int k = tid >> 4, c = tid & 15;                    // 512 items
        int col = n0 + c * 8;
        const float* bb = headStride ? (B + (long)(col >> 6) * headStride + (col & 63))
                                     : (B + col);
        bptr = bb + (long)(k0 + k) * rowStr;
        bsto = ABYTES + boff<128>(k, c);
    }

    const int aRowL = lane & 15, aChL = lane >> 4;
    uint32_t sbase[2] = { smem_u32(&sm[0][0]), smem_u32(&sm[1][0]) };

    float acc[4][4][4];
#pragma unroll
    for (int i = 0; i < 4; i++)
#pragma unroll
        for (int j = 0; j < 4; j++)
#pragma unroll
            for (int l = 0; l < 4; l++) acc[i][j][l] = 0.f;

    uint4 rau[2]; float4 rb0, rb1;

    // prologue: stage tile 0
#pragma unroll
    for (int i = 0; i < 2; i++) rau[i] = *(const uint4*)(aptr[i]);
    rb0 = *(const float4*)(bptr);
    rb1 = *(const float4*)(bptr + 4);
#pragma unroll
    for (int i = 0; i < 2; i++) *(uint4*)&sm[0][asto[i]] = rau[i];
    {
        uint4 u;
        u.x = pack2(rb0.x, rb0.y); u.y = pack2(rb0.z, rb0.w);
        u.z = pack2(rb1.x, rb1.y); u.w = pack2(rb1.z, rb1.w);
        *(uint4*)&sm[0][bsto] = u;
    }
    __syncthreads();

    for (int t = 0; t < kIters; t++) {
        if (t + 1 < kIters) {
            const long ka = (long)(t + 1) * 32;
            const long kbb = (long)(t + 1) * 32 * rowStr;
#pragma unroll
            for (int i = 0; i < 2; i++) rau[i] = *(const uint4*)(aptr[i] + ka);
            rb0 = *(const float4*)(bptr + kbb);
            rb1 = *(const float4*)(bptr + kbb + 4);
        }
        const uint32_t sa = sbase[t & 1];
        const uint32_t sbB = sbase[t & 1] + ABYTES;
#pragma unroll
        for (int kk = 0; kk < 2; kk++) {
            uint32_t af[4][4], bf[2][4];
#pragma unroll
            for (int mt = 0; mt < 4; mt++)
                ldsm_x4(af[mt], sa + aoff(wm * 64 + mt * 16 + aRowL, kk * 2 + aChL));
#pragma unroll
            for (int ntp = 0; ntp < 2; ntp++)
                ldsm_x4_t(bf[ntp], sbB + boff<128>(kk * 16 + aRowL,
                                                   wn * 4 + ntp * 2 + aChL));
#pragma unroll
            for (int mt = 0; mt < 4; mt++)
#pragma unroll
                for (int ntp = 0; ntp < 2; ntp++) {
                    mma_fp16(acc[mt][ntp * 2 + 0], af[mt], &bf[ntp][0]);
                    mma_fp16(acc[mt][ntp * 2 + 1], af[mt], &bf[ntp][2]);
                }
        }
        if (t + 1 < kIters) {
            char* d = sm[(t + 1) & 1];
#pragma unroll
            for (int i = 0; i < 2; i++) *(uint4*)&d[asto[i]] = rau[i];
            uint4 u;
            u.x = pack2(rb0.x, rb0.y); u.y = pack2(rb0.z, rb0.w);
            u.z = pack2(rb1.x, rb1.y); u.w = pack2(rb1.z, rb1.w);
            *(uint4*)&d[bsto] = u;
            __syncthreads();
        }
    }

    // epilogue
#pragma unroll
    for (int mt = 0; mt < 4; mt++) {
        int r0 = m0 + wm * 64 + mt * 16 + gid;
#pragma unroll
        for (int nt = 0; nt < 4; nt++) {
            int col = n0 + wn * 32 + nt * 8 + tg * 2;
            float2 v0 = make_float2(acc[mt][nt][0], acc[mt][nt][1]);
            float2 v1 = make_float2(acc[mt][nt][2], acc[mt][nt][3]);
            if (bias) {
                float2 bv = *(const float2*)(bias + col);
                v0.x += bv.x; v0.y += bv.y; v1.x += bv.x; v1.y += bv.y;
            }
            if (OH) {
                __half* Ch = (__half*)Cv;
                *(__half2*)(Ch + (long)r0 * ldc + col) = __floats2half2_rn(v0.x, v0.y);
                *(__half2*)(Ch + (long)(r0 + 8) * ldc + col) = __floats2half2_rn(v1.x, v1.y);
            } else {
                float* Cp = (float*)Cv + (long)blockIdx.z * cSplit;
                if (resid) {
                    float2 q0 = *(const float2*)(resid + (long)r0 * ldc + col);
                    float2 q1 = *(const float2*)(resid + (long)(r0 + 8) * ldc + col);
                    v0.x += q0.x; v0.y += q0.y; v1.x += q1.x; v1.y += q1.y;
                }
                if (relu) {
                    v0.x = fmaxf(v0.x, 0.f); v0.y = fmaxf(v0.y, 0.f);
                    v1.x = fmaxf(v1.x, 0.f); v1.y = fmaxf(v1.y, 0.f);
                }
                *(float2*)(Cp + (long)r0 * ldc + col) = v0;
                *(float2*)(Cp + (long)(r0 + 8) * ldc + col) = v1;
            }
        }
    }
}

// ------------------------------------------------------------------
// Small fp16 GEMM (Wf): BM=128, BN=64, BK=32, 256 thr (8 warps 4x2).
// ------------------------------------------------------------------
__global__ __launch_bounds__(256) void gemm16s(
    const __half* __restrict__ A, int lda,
    const float* __restrict__ B, int ldb,
    float* __restrict__ C, int ldc,
    int kIters, int kChunk, long cSplit)
{
    constexpr int ABYTES = 128 * 64;
    constexpr int BBYTES = 32 * 128;
    __shared__ char sm[2][ABYTES + BBYTES];

    const int tid = threadIdx.x;
    const int m0 = blockIdx.y * 128;
    const int n0 = blockIdx.x * 64;
    const int k0 = blockIdx.z * kChunk;
    const int warp = tid >> 5, lane = tid & 31;
    const int wm = warp >> 1, wn = warp & 1;
    const int gid = lane >> 2, tg = lane & 3;

    const __half* aptr[2]; int asto[2];
#pragma unroll
    for (int i = 0; i < 2; i++) {
        int id = tid + i * 256, r = id >> 2, c = id & 3;
        aptr[i] = A + (long)(m0 + r) * lda + k0 + c * 8;
        asto[i] = aoff(r, c);
    }
    const float* bptr; int bsto;
    {
        int k = tid >> 3, c = tid & 7;
        bptr = B + (long)(k0 + k) * ldb + n0 + c * 8;
        bsto = ABYTES + boff<64>(k, c);
    }

    const int aRowL = lane & 15, aChL = lane >> 4;
    uint32_t sbase[2] = { smem_u32(&sm[0][0]), smem_u32(&sm[1][0]) };

    float acc[2][4][4];
#pragma unroll
    for (int i = 0; i < 2; i++)
#pragma unroll
        for (int j = 0; j < 4; j++)
#pragma unroll
            for (int l = 0; l < 4; l++) acc[i][j][l] = 0.f;

    uint4 rau[2]; float4 rb0, rb1;
#pragma unroll
    for (int i = 0; i < 2; i++) rau[i] = *(const uint4*)(aptr[i]);
    rb0 = *(const float4*)(bptr);
    rb1 = *(const float4*)(bptr + 4);
#pragma unroll
    for (int i = 0; i < 2; i++) *(uint4*)&sm[0][asto[i]] = rau[i];
    {
        uint4 u;
        u.x = pack2(rb0.x, rb0.y); u.y = pack2(rb0.z, rb0.w);
        u.z = pack2(rb1.x, rb1.y); u.w = pack2(rb1.z, rb1.w);
        *(uint4*)&sm[0][bsto] = u;
    }
    __syncthreads();

    for (int t = 0; t < kIters; t++) {
        if (t + 1 < kIters) {
            const long ka = (long)(t + 1) * 32;
            const long kbb = (long)(t + 1) * 32 * ldb;
#pragma unroll
            for (int i = 0; i < 2; i++) rau[i] = *(const uint4*)(aptr[i] + ka);
            rb0 = *(const float4*)(bptr + kbb);
            rb1 = *(const float4*)(bptr + kbb + 4);
        }
        const uint32_t sa = sbase[t & 1];
        const uint32_t sbB = sbase[t & 1] + ABYTES;
#pragma unroll
        for (int kk = 0; kk < 2; kk++) {
            uint32_t af[2][4], bf[2][4];
#pragma unroll
            for (int mt = 0; mt < 2; mt++)
                ldsm_x4(af[mt], sa + aoff(wm * 32 + mt * 16 + aRowL, kk * 2 + aChL));
#pragma unroll
            for (int ntp = 0; ntp < 2; ntp++)
                ldsm_x4_t(bf[ntp], sbB + boff<64>(kk * 16 + aRowL,
                                                  wn * 4 + ntp * 2 + aChL));
#pragma unroll
            for (int mt = 0; mt < 2; mt++)
#pragma unroll
                for (int ntp = 0; ntp < 2; ntp++) {
                    mma_fp16(acc[mt][ntp * 2 + 0], af[mt], &bf[ntp][0]);
                    mma_fp16(acc[mt][ntp * 2 + 1], af[mt], &bf[ntp][2]);
                }
        }
        if (t + 1 < kIters) {
            char* d = sm[(t + 1) & 1];
#pragma unroll
            for (int i = 0; i < 2; i++) *(uint4*)&d[asto[i]] = rau[i];
            uint4 u;
            u.x = pack2(rb0.x, rb0.y); u.y = pack2(rb0.z, rb0.w);
            u.z = pack2(rb1.x, rb1.y); u.w = pack2(rb1.z, rb1.w);
            *(uint4*)&d[bsto] = u;
            __syncthreads();
        }
    }

    float* Cp = C + (long)blockIdx.z * cSplit;
#pragma unroll
    for (int mt = 0; mt < 2; mt++) {
        int r0 = m0 + wm * 32 + mt * 16 + gid;
#pragma unroll
        for (int nt = 0; nt < 4; nt++) {
            int col = n0 + wn * 32 + nt * 8 + tg * 2;
            *(float2*)(Cp + (long)r0 * ldc + col) =
                make_float2(acc[mt][nt][0], acc[mt][nt][1]);
            *(float2*)(Cp + (long)(r0 + 8) * ldc + col) =
                make_float2(acc[mt][nt][2], acc[mt][nt][3]);
        }
    }
}

// ------------------------------------------------------------------
// MMA attention per (b,h): 128 threads (4 warps), fp16 in/out, fp32 acc.
// ------------------------------------------------------------------
__global__ __launch_bounds__(128) void attn_mma(
    const __half* __restrict__ Qh, const __half* __restrict__ Kh,
    const __half* __restrict__ Vh, __half* __restrict__ Ctx)
{
    __shared__ __align__(16) char sq[64 * 128], sk[64 * 128], sv[64 * 128];
    const int tid = threadIdx.x;
    const int w = tid >> 5, lane = tid & 31;
    const int gid = lane >> 2, tg = lane & 3;
    const int b = blockIdx.x >> 3, h = blockIdx.x & 7;
    const long base = (long)(b * 64) * 512 + h * 64;

#pragma unroll
    for (int i = 0; i < 4; i++) {
        int id = tid + i * 128, r = id >> 3, c = id & 7;
        int so = foff(r, c);
        const long go = base + (long)r * 512 + c * 8;
        *(uint4*)(sq + so) = *(const uint4*)(Qh + go);
        *(uint4*)(sk + so) = *(const uint4*)(Kh + go);
        *(uint4*)(sv + so) = *(const uint4*)(Vh + go);
    }
    __syncthreads();

    const uint32_t sqb = smem_u32(sq), skb = smem_u32(sk), svb = smem_u32(sv);
    const int rowL = lane & 15, chL = lane >> 4;

    float sacc[8][4];
#pragma unroll
    for (int j = 0; j < 8; j++)
#pragma unroll
        for (int l = 0; l < 4; l++) sacc[j][l] = 0.f;
#pragma unroll
    for (int kk = 0; kk < 4; kk++) {
        uint32_t a[4];
        ldsm_x4(a, sqb + foff(w * 16 + rowL, kk * 2 + chL));
#pragma unroll
        for (int g = 0; g < 4; g++) {
            uint32_t bk[4];
            ldsm_x4(bk, skb + foff(g * 16 + rowL, kk * 2 + chL));
            mma_fp16_2(sacc[g * 2 + 0], a, bk[0], bk[2]);
            mma_fp16_2(sacc[g * 2 + 1], a, bk[1], bk[3]);
        }
    }

    float mx0 = -1e30f, mx1 = -1e30f;
#pragma unroll
    for (int j = 0; j < 8; j++) {
#pragma unroll
        for (int l = 0; l < 4; l++) sacc[j][l] *= 0.125f;
        mx0 = fmaxf(mx0, fmaxf(sacc[j][0], sacc[j][1]));
        mx1 = fmaxf(mx1, fmaxf(sacc[j][2], sacc[j][3]));
    }
#pragma unroll
    for (int o = 1; o < 4; o <<= 1) {
        mx0 = fmaxf(mx0, __shfl_xor_sync(~0u, mx0, o));
        mx1 = fmaxf(mx1, __shfl_xor_sync(~0u, mx1, o));
    }
    float s0 = 0.f, s1 = 0.f;
#pragma unroll
    for (int j = 0; j < 8; j++) {
        sacc[j][0] = __expf(sacc[j][0] - mx0);
        sacc[j][1] = __expf(sacc[j][1] - mx0);
        sacc[j][2] = __expf(sacc[j][2] - mx1);
        sacc[j][3] = __expf(sacc[j][3] - mx1);
        s0 += sacc[j][0] + sacc[j][1];
        s1 += sacc[j][2] + sacc[j][3];
    }
#pragma unroll
    for (int o = 1; o < 4; o <<= 1) {
        s0 += __shfl_xor_sync(~0u, s0, o);
        s1 += __shfl_xor_sync(~0u, s1, o);
    }
    const float r0 = 1.f / s0, r1 = 1.f / s1;

    uint32_t ap[4][4];
#pragma unroll
    for (int kk = 0; kk < 4; kk++) {
        ap[kk][0] = pack2(sacc[kk * 2][0], sacc[kk * 2][1]);
        ap[kk][1] = pack2(sacc[kk * 2][2], sacc[kk * 2][3]);
        ap[kk][2] = pack2(sacc[kk * 2 + 1][0], sacc[kk * 2 + 1][1]);
        ap[kk][3] = pack2(sacc[kk * 2 + 1][2], sacc[kk * 2 + 1][3]);
    }

    float cacc[8][4];
#pragma unroll
    for (int j = 0; j < 8; j++)
#pragma unroll
        for (int l = 0; l < 4; l++) cacc[j][l] = 0.f;
#pragma unroll
    for (int kk = 0; kk < 4; kk++) {
#pragma unroll
        for (int g = 0; g < 4; g++) {
            uint32_t bv[4];
            ldsm_x4_t(bv, svb + foff(kk * 16 + rowL, g * 2 + chL));
            mma_fp16_2(cacc[g * 2 + 0], ap[kk], bv[0], bv[1]);
            mma_fp16_2(cacc[g * 2 + 1], ap[kk], bv[2], bv[3]);
        }
    }

    const long orow0 = (long)(b * 64 + w * 16 + gid) * 512 + h * 64;
    const long orow1 = orow0 + 8 * 512;
#pragma unroll
    for (int nt = 0; nt < 8; nt++) {
        int col = nt * 8 + tg * 2;
        *(__half2*)(Ctx + orow0 + col) = __floats2half2_rn(cacc[nt][0] * r0, cacc[nt][1] * r0);
        *(__half2*)(Ctx + orow1 + col) = __floats2half2_rn(cacc[nt][2] * r1, cacc[nt][3] * r1);
    }
}

// ---------------- fp32 -> fp16 bulk convert ----------------
__global__ void cvt_f2h(const float* __restrict__ in, __half* __restrict__ out)
{
    int idx = blockIdx.x * 256 + threadIdx.x;
    float4 f = ((const float4*)in)[idx];
    __half2* o = (__half2*)out + idx * 2;
    o[0] = __floats2half2_rn(f.x, f.y);
    o[1] = __floats2half2_rn(f.z, f.w);
}

// ---------------- LayerNorm width=512, dual fp32+fp16 out ----------------
__global__ __launch_bounds__(256) void ln512_dual(
    const float* __restrict__ in, float* __restrict__ out, __half* __restrict__ outh,
    const float* __restrict__ gam, const float* __restrict__ bet)
{
    const int row = blockIdx.x * 8 + (threadIdx.x >> 5);
    const int lane = threadIdx.x & 31;
    const float* p = in + (long)row * 512;
    float v[16], s = 0.f, s2 = 0.f;
#pragma unroll
    for (int i = 0; i < 16; i++) {
        v[i] = p[lane + 32 * i]; s += v[i]; s2 = fmaf(v[i], v[i], s2);
    }
#pragma unroll
    for (int o = 16; o > 0; o >>= 1) {
        s += __shfl_xor_sync(~0u, s, o); s2 += __shfl_xor_sync(~0u, s2, o);
    }
    float mu = s * (1.f / 512.f);
    float rsg = rsqrtf(s2 * (1.f / 512.f) - mu * mu + 1e-5f);
    float* q = out + (long)row * 512;
    __half* qh = outh + (long)row * 512;
#pragma unroll
    for (int i = 0; i < 16; i++) {
        int c = lane + 32 * i;
        float r = (v[i] - mu) * rsg * gam[c] + bet[c];
        q[c] = r;
        qh[c] = __float2half_rn(r);
    }
}

// ---------------- LayerNorm width=32768, fp16 out ----------------
__global__ __launch_bounds__(1024) void ln32k_h(
    const float* __restrict__ in, __half* __restrict__ out,
    const float* __restrict__ gam, const float* __restrict__ bet)
{
    __shared__ float rs1[32], rs2[32], stat[2];
    const int row = blockIdx.x;
    const float* p = in + (long)row * 32768;
    float s = 0.f, s2 = 0.f;
    for (int i = threadIdx.x; i < 32768; i += 1024) {
        float v = p[i]; s += v; s2 = fmaf(v, v, s2);
    }
#pragma unroll
    for (int o = 16; o > 0; o >>= 1) {
        s += __shfl_xor_sync(~0u, s, o); s2 += __shfl_xor_sync(~0u, s2, o);
    }
    if ((threadIdx.x & 31) == 0) { rs1[threadIdx.x >> 5] = s; rs2[threadIdx.x >> 5] = s2; }
    __syncthreads();
    if (threadIdx.x < 32) {
        s = rs1[threadIdx.x]; s2 = rs2[threadIdx.x];
#pragma unroll
        for (int o = 16; o > 0; o >>= 1) {
            s += __shfl_xor_sync(~0u, s, o); s2 += __shfl_xor_sync(~0u, s2, o);
        }
        if (threadIdx.x == 0) {
            float mu = s * (1.f / 32768.f);
            stat[0] = mu; stat[1] = rsqrtf(s2 * (1.f / 32768.f) - mu * mu + 1e-5f);
        }
    }
    __syncthreads();
    float mu = stat[0], rsg = stat[1];
    __half* q = out + (long)row * 32768;
    for (int i = threadIdx.x; i < 32768; i += 1024)
        q[i] = __float2half_rn((p[i] - mu) * rsg * gam[i] + bet[i]);
}

// ---------------- reducers ----------------
__global__ void reduce16_relu_h(const float* __restrict__ part,
                                const float* __restrict__ b1, __half* __restrict__ out)
{
    int idx = blockIdx.x * 256 + threadIdx.x;  // < 524288
    float s = 0.f;
#pragma unroll
    for (int z = 0; z < 16; z++) s += part[(long)z * 524288 + idx];
    s += b1[idx & 2047];
    out[idx] = __float2half_rn(fmaxf(s, 0.f));
}

__global__ void reduce_out_k(const float* __restrict__ part,
                             const float* __restrict__ bf, float* __restrict__ out)
{
    int idx = blockIdx.x * 256 + threadIdx.x;
    if (idx >= 12800) return;
    int m = idx / 50, j = idx % 50;
    float s = bf[j];
#pragma unroll
    for (int z = 0; z < 64; z++) s += part[(long)z * 16384 + m * 64 + j];
    out[idx] = s;
}

__global__ void pad_wf_k(const float* __restrict__ Wf, float* __restrict__ Wfp)
{
    int idx = blockIdx.x * 256 + threadIdx.x;  // < 32768*64
    int k = idx >> 6, j = idx & 63;
    Wfp[idx] = (j < 50) ? Wf[k * 50 + j] : 0.f;
}

// ------------------------------------------------------------------
extern "C" void kernel_launch(void* const* d_in, const int* in_sizes, int n_in,
                              void* d_out, int out_size)
{
    const float* inputs = (const float*)d_in[0];
    const float* Wq = (const float*)d_in[1];  const float* bq = (const float*)d_in[2];
    const float* Wk = (const float*)d_in[3];  const float* bk = (const float*)d_in[4];
    const float* Wv = (const float*)d_in[5];  const float* bv = (const float*)d_in[6];
    const float* Wo = (const float*)d_in[7];  const float* bo = (const float*)d_in[8];
    const float* ln1g = (const float*)d_in[9];  const float* ln1b = (const float*)d_in[10];
    const float* W1 = (const float*)d_in[11]; const float* b1 = (const float*)d_in[12];
    const float* W2 = (const float*)d_in[13]; const float* b2 = (const float*)d_in[14];
    const float* ln2g = (const float*)d_in[15]; const float* ln2b = (const float*)d_in[16];
    const float* Wf = (const float*)d_in[17]; const float* bf = (const float*)d_in[18];
    float* out = (float*)d_out;

    __half *inh, *qh, *kh, *vh, *ctxh, *xh, *hh, *yh;
    float *res1, *x, *p4, *v2, *wfp, *p6;
    cudaGetSymbolAddress((void**)&inh, g_inh);
    cudaGetSymbolAddress((void**)&qh, g_qh);
    cudaGetSymbolAddress((void**)&kh, g_kh);
    cudaGetSymbolAddress((void**)&vh, g_vh);
    cudaGetSymbolAddress((void**)&ctxh, g_ctxh);
    cudaGetSymbolAddress((void**)&xh, g_xh);
    cudaGetSymbolAddress((void**)&hh, g_hh);
    cudaGetSymbolAddress((void**)&yh, g_yh);
    cudaGetSymbolAddress((void**)&res1, g_res1);
    cudaGetSymbolAddress((void**)&x, g_x);
    cudaGetSymbolAddress((void**)&p4, g_p4);
    cudaGetSymbolAddress((void**)&v2, g_v2);
    cudaGetSymbolAddress((void**)&wfp, g_wfp);
    cudaGetSymbolAddress((void**)&p6, g_p6);

    // independent prep
    pad_wf_k<<<8192, 256>>>(Wf, wfp);
    cvt_f2h<<<8192, 256>>>(inputs, inh);

    // QKV projections -> fp16 outputs (BM=256, BN=128)
    gemm512<true><<<dim3(4, 64, 1), 512>>>(inh, 512, Wq, 64, 32768,
                                           qh, 512, 16, 0, 0, bq, nullptr, 0);
    gemm512<true><<<dim3(4, 64, 1), 512>>>(inh, 512, Wk, 64, 32768,
                                           kh, 512, 16, 0, 0, bk, nullptr, 0);
    gemm512<true><<<dim3(4, 64, 1), 512>>>(inh, 512, Wv, 64, 32768,
                                           vh, 512, 16, 0, 0, bv, nullptr, 0);

    // MMA attention
    attn_mma<<<2048, 128>>>(qh, kh, vh, ctxh);

    // output projection + bias + residual(inputs) -> fp32
    gemm512<false><<<dim3(4, 64, 1), 512>>>(ctxh, 512, Wo, 512, 0,
                                            res1, 512, 16, 0, 0, bo, inputs, 0);

    // LN1 -> x (fp32) + xh (fp16)
    ln512_dual<<<2048, 256>>>(res1, x, xh, ln1g, ln1b);

    // h = relu(x @ W1 + b1): M=256 (one block), split-K 16
    gemm512<false><<<dim3(16, 1, 16), 512>>>(xh, 32768, W1, 2048, 0,
                                             p4, 2048, 64, 2048, 524288,
                                             nullptr, nullptr, 0);
    reduce16_relu_h<<<2048, 256>>>(p4, b1, hh);

    // v2 = h @ W2 + b2 + x -> fp32
    gemm512<false><<<dim3(256, 1, 1), 512>>>(hh, 2048, W2, 32768, 0,
                                             v2, 32768, 64, 0, 0, b2, x, 0);

    // LN2 -> yh fp16
    ln32k_h<<<256, 1024>>>(v2, yh, ln2g, ln2b);

    // logits: y @ wfp split-K 64
    gemm16s<<<dim3(1, 2, 64), 256>>>(yh, 32768, wfp, 64, p6, 64, 16, 512, 16384);
    reduce_out_k<<<50, 256>>>(p6, bf, out);
}

// round 13
// speedup vs baseline: 2.7915x; 1.0442x over previous
#include <cuda_runtime.h>
#include <cuda_fp16.h>
#include <cstdint>

// B=256, S=64, D=512, H=8, DK=DV=64, DFF=2048, IN=32768, OUT=50

// ---------------- device scratch (static, no allocation) ----------------
__device__ __half g_inh [16384L*512];
__device__ __half g_qh  [16384L*512];
__device__ __half g_kh  [16384L*512];
__device__ __half g_vh  [16384L*512];
__device__ __half g_ctxh[16384L*512];
__device__ __half g_xh  [256L*32768];
__device__ __half g_hh  [256L*2048];
__device__ __half g_yh  [256L*32768];
__device__ __half g_wqh [8L*512*64];
__device__ __half g_wkh [8L*512*64];
__device__ __half g_wvh [8L*512*64];
__device__ __half g_woh [512L*512];
__device__ float  g_res1[16384L*512];
__device__ float  g_x   [16384L*512];
__device__ float  g_p4  [16L*256*2048];
__device__ float  g_v2  [256L*32768];
__device__ float  g_wfp [32768L*64];
__device__ float  g_p6  [64L*256*64];

// ---------------- helpers ----------------
__device__ __forceinline__ uint32_t pack2(float a, float b) {
    __half2 h = __floats2half2_rn(a, b);
    return *reinterpret_cast<uint32_t*>(&h);
}
__device__ __forceinline__ int aoff(int r, int c) {   // A: 64B rows, paired atoms
    return ((r >> 1) << 7) + (((((r & 1) << 2) + c) ^ ((r >> 1) & 7)) << 4);
}
template<int BN>
__device__ __forceinline__ int boff(int k, int c) {   // B: 2*BN B rows
    return k * (2 * BN) + ((((c & ~7) | ((c ^ (k & 7)) & 7))) << 4);
}
__device__ __forceinline__ int foff(int r, int c) {   // 128B rows (attention)
    return (r << 7) + (((c ^ (r & 7)) & 7) << 4);
}
__device__ __forceinline__ void ldsm_x4(uint32_t* r, uint32_t addr) {
    asm volatile("ldmatrix.sync.aligned.m8n8.x4.shared.b16 {%0,%1,%2,%3}, [%4];"
                 : "=r"(r[0]), "=r"(r[1]), "=r"(r[2]), "=r"(r[3]) : "r"(addr));
}
__device__ __forceinline__ void ldsm_x4_t(uint32_t* r, uint32_t addr) {
    asm volatile("ldmatrix.sync.aligned.m8n8.x4.trans.shared.b16 {%0,%1,%2,%3}, [%4];"
                 : "=r"(r[0]), "=r"(r[1]), "=r"(r[2]), "=r"(r[3]) : "r"(addr));
}
__device__ __forceinline__ void mma_fp16(float* d, const uint32_t* a, const uint32_t* b) {
    asm volatile(
        "mma.sync.aligned.m16n8k16.row.col.f32.f16.f16.f32 "
        "{%0,%1,%2,%3},{%4,%5,%6,%7},{%8,%9},{%0,%1,%2,%3};"
        : "+f"(d[0]), "+f"(d[1]), "+f"(d[2]), "+f"(d[3])
        : "r"(a[0]), "r"(a[1]), "r"(a[2]), "r"(a[3]), "r"(b[0]), "r"(b[1]));
}
__device__ __forceinline__ void mma_fp16_2(float* d, const uint32_t* a, uint32_t b0, uint32_t b1) {
    asm volatile(
        "mma.sync.aligned.m16n8k16.row.col.f32.f16.f16.f32 "
        "{%0,%1,%2,%3},{%4,%5,%6,%7},{%8,%9},{%0,%1,%2,%3};"
        : "+f"(d[0]), "+f"(d[1]), "+f"(d[2]), "+f"(d[3])
        : "r"(a[0]), "r"(a[1]), "r"(a[2]), "r"(a[3]), "r"(b0), "r"(b1));
}
__device__ __forceinline__ uint32_t smem_u32(const void* p) {
    uint32_t a;
    asm("{ .reg .u64 t; cvta.to.shared.u64 t, %1; cvt.u32.u64 %0, t; }" : "=r"(a) : "l"(p));
    return a;
}
__device__ __forceinline__ void cp16(uint32_t saddr, const void* g) {
    asm volatile("cp.async.cg.shared.global [%0], [%1], 16;" :: "r"(saddr), "l"(g));
}
#define CP_COMMIT() asm volatile("cp.async.commit_group;" ::: "memory")
#define CP_WAIT2()  asm volatile("cp.async.wait_group 2;" ::: "memory")

// ------------------------------------------------------------------
// cp.async 4-stage fp16 GEMM: BM=256, BN=128, BK=32, 512 thr (4x4 warps).
// A fp16 [*,lda], B fp16 (headStride: per-head [H][K][64], in halves).
// Dynamic smem: 4 stages x 24576 B.
// ------------------------------------------------------------------
template<bool OH>
__global__ __launch_bounds__(512) void gemma(
    const __half* __restrict__ A, int lda,
    const __half* __restrict__ B, int ldb, int headStride,
    void* __restrict__ Cv, int ldc, int kIters,
    const float* __restrict__ bias,
    const float* __restrict__ resid)
{
    constexpr int ABYTES = 256 * 64;       // 16384
    constexpr int STAGE  = ABYTES + 32 * 256;  // +8192 = 24576
    extern __shared__ char smx[];
    const uint32_t sb = smem_u32(smx);

    const int tid = threadIdx.x;
    const int m0 = blockIdx.y * 256;
    const int n0 = blockIdx.x * 128;
    const int warp = tid >> 5, lane = tid & 31;
    const int wm = warp >> 2, wn = warp & 3;
    const int gid = lane >> 2, tg = lane & 3;

    // cp.async assignments
    const __half* aptr[2]; uint32_t asto[2];
#pragma unroll
    for (int i = 0; i < 2; i++) {
        int id = tid + i * 512, r = id >> 2, c = id & 3;
        aptr[i] = A + (long)(m0 + r) * lda + c * 8;
        asto[i] = aoff(r, c);
    }
    const int rowStr = headStride ? 64 : ldb;
    const __half* bptr; uint32_t bsto;
    {
        int k = tid >> 4, c = tid & 15;
        int col = n0 + c * 8;
        const __half* bb = headStride ? (B + (long)(col >> 6) * headStride + (col & 63))
                                      : (B + col);
        bptr = bb + (long)k * rowStr;
        bsto = ABYTES + boff<128>(k, c);
    }

    const int aRowL = lane & 15, aChL = lane >> 4;

    float acc[4][4][4];
#pragma unroll
    for (int i = 0; i < 4; i++)
#pragma unroll
        for (int j = 0; j < 4; j++)
#pragma unroll
            for (int l = 0; l < 4; l++) acc[i][j][l] = 0.f;

    // prologue: stages 0..2
#pragma unroll
    for (int s = 0; s < 3; s++) {
        const uint32_t st = sb + s * STAGE;
        const long ka = (long)s * 32;
        cp16(st + asto[0], aptr[0] + ka);
        cp16(st + asto[1], aptr[1] + ka);
        cp16(st + bsto, bptr + ka * rowStr);
        CP_COMMIT();
    }

    for (int t = 0; t < kIters; t++) {
        CP_WAIT2();
        __syncthreads();
        if (t + 3 < kIters) {
            const uint32_t st = sb + ((t + 3) & 3) * STAGE;
            const long ka = (long)(t + 3) * 32;
            cp16(st + asto[0], aptr[0] + ka);
            cp16(st + asto[1], aptr[1] + ka);
            cp16(st + bsto, bptr + ka * rowStr);
        }
        CP_COMMIT();
        const uint32_t sa = sb + (t & 3) * STAGE;
        const uint32_t sbB = sa + ABYTES;
#pragma unroll
        for (int kk = 0; kk < 2; kk++) {
            uint32_t af[4][4], bf[2][4];
#pragma unroll
            for (int mt = 0; mt < 4; mt++)
                ldsm_x4(af[mt], sa + aoff(wm * 64 + mt * 16 + aRowL, kk * 2 + aChL));
#pragma unroll
            for (int ntp = 0; ntp < 2; ntp++)
                ldsm_x4_t(bf[ntp], sbB + boff<128>(kk * 16 + aRowL,
                                                   wn * 4 + ntp * 2 + aChL));
#pragma unroll
            for (int mt = 0; mt < 4; mt++)
#pragma unroll
                for (int ntp = 0; ntp < 2; ntp++) {
                    mma_fp16(acc[mt][ntp * 2 + 0], af[mt], &bf[ntp][0]);
                    mma_fp16(acc[mt][ntp * 2 + 1], af[mt], &bf[ntp][2]);
                }
        }
    }

    // epilogue
#pragma unroll
    for (int mt = 0; mt < 4; mt++) {
        int r0 = m0 + wm * 64 + mt * 16 + gid;
#pragma unroll
        for (int nt = 0; nt < 4; nt++) {
            int col = n0 + wn * 32 + nt * 8 + tg * 2;
            float2 v0 = make_float2(acc[mt][nt][0], acc[mt][nt][1]);
            float2 v1 = make_float2(acc[mt][nt][2], acc[mt][nt][3]);
            if (bias) {
                float2 bv = *(const float2*)(bias + col);
                v0.x += bv.x; v0.y += bv.y; v1.x += bv.x; v1.y += bv.y;
            }
            if (OH) {
                __half* Ch = (__half*)Cv;
                *(__half2*)(Ch + (long)r0 * ldc + col) = __floats2half2_rn(v0.x, v0.y);
                *(__half2*)(Ch + (long)(r0 + 8) * ldc + col) = __floats2half2_rn(v1.x, v1.y);
            } else {
                float* Cp = (float*)Cv;
                if (resid) {
                    float2 q0 = *(const float2*)(resid + (long)r0 * ldc + col);
                    float2 q1 = *(const float2*)(resid + (long)(r0 + 8) * ldc + col);
                    v0.x += q0.x; v0.y += q0.y; v1.x += q1.x; v1.y += q1.y;
                }
                *(float2*)(Cp + (long)r0 * ldc + col) = v0;
                *(float2*)(Cp + (long)(r0 + 8) * ldc + col) = v1;
            }
        }
    }
}

// ------------------------------------------------------------------
// fp32-B GEMM (W1/W2): BM=256, BN=128, BK=32, 512 thr, double-buffered.
// ------------------------------------------------------------------
__global__ __launch_bounds__(512) void gemm512(
    const __half* __restrict__ A, int lda,
    const float* __restrict__ B, int ldb,
    float* __restrict__ C, int ldc,
    int kIters, int kChunk, long cSplit,
    const float* __restrict__ bias,
    const float* __restrict__ resid,
    int relu)
{
    constexpr int ABYTES = 256 * 64;
    constexpr int BBYTES = 32 * 256;
    __shared__ char sm[2][ABYTES + BBYTES];

    const int tid = threadIdx.x;
    const int m0 = blockIdx.y * 256;
    const int n0 = blockIdx.x * 128;
    const int k0 = blockIdx.z * kChunk;
    const int warp = tid >> 5, lane = tid & 31;
    const int wm = warp >> 2, wn = warp & 3;
    const int gid = lane >> 2, tg = lane & 3;

    const __half* aptr[2]; int asto[2];
#pragma unroll
    for (int i = 0; i < 2; i++) {
        int id = tid + i * 512, r = id >> 2, c = id & 3;
        aptr[i] = A + (long)(m0 + r) * lda + k0 + c * 8;
        asto[i] = aoff(r, c);
    }
    const float* bptr; int bsto;
    {
        int k = tid >> 4, c = tid & 15;
        bptr = B + (long)(k0 + k) * ldb + n0 + c * 8;
        bsto = ABYTES + boff<128>(k, c);
    }

    const int aRowL = lane & 15, aChL = lane >> 4;
    uint32_t sbase[2] = { smem_u32(&sm[0][0]), smem_u32(&sm[1][0]) };

    float acc[4][4][4];
#pragma unroll
    for (int i = 0; i < 4; i++)
#pragma unroll
        for (int j = 0; j < 4; j++)
#pragma unroll
            for (int l = 0; l < 4; l++) acc[i][j][l] = 0.f;

    uint4 rau[2]; float4 rb0, rb1;
#pragma unroll
    for (int i = 0; i < 2; i++) rau[i] = *(const uint4*)(aptr[i]);
    rb0 = *(const float4*)(bptr);
    rb1 = *(const float4*)(bptr + 4);
#pragma unroll
    for (int i = 0; i < 2; i++) *(uint4*)&sm[0][asto[i]] = rau[i];
    {
        uint4 u;
        u.x = pack2(rb0.x, rb0.y); u.y = pack2(rb0.z, rb0.w);
        u.z = pack2(rb1.x, rb1.y); u.w = pack2(rb1.z, rb1.w);
        *(uint4*)&sm[0][bsto] = u;
    }
    __syncthreads();

    for (int t = 0; t < kIters; t++) {
        if (t + 1 < kIters) {
            const long ka = (long)(t + 1) * 32;
            const long kbb = (long)(t + 1) * 32 * ldb;
#pragma unroll
            for (int i = 0; i < 2; i++) rau[i] = *(const uint4*)(aptr[i] + ka);
            rb0 = *(const float4*)(bptr + kbb);
            rb1 = *(const float4*)(bptr + kbb + 4);
        }
        const uint32_t sa = sbase[t & 1];
        const uint32_t sbB = sbase[t & 1] + ABYTES;
#pragma unroll
        for (int kk = 0; kk < 2; kk++) {
            uint32_t af[4][4], bf[2][4];
#pragma unroll
            for (int mt = 0; mt < 4; mt++)
                ldsm_x4(af[mt], sa + aoff(wm * 64 + mt * 16 + aRowL, kk * 2 + aChL));
#pragma unroll
            for (int ntp = 0; ntp < 2; ntp++)
                ldsm_x4_t(bf[ntp], sbB + boff<128>(kk * 16 + aRowL,
                                                   wn * 4 + ntp * 2 + aChL));
#pragma unroll
            for (int mt = 0; mt < 4; mt++)
#pragma unroll
                for (int ntp = 0; ntp < 2; ntp++) {
                    mma_fp16(acc[mt][ntp * 2 + 0], af[mt], &bf[ntp][0]);
                    mma_fp16(acc[mt][ntp * 2 + 1], af[mt], &bf[ntp][2]);
                }
        }
        if (t + 1 < kIters) {
            char* d = sm[(t + 1) & 1];
#pragma unroll
            for (int i = 0; i < 2; i++) *(uint4*)&d[asto[i]] = rau[i];
            uint4 u;
            u.x = pack2(rb0.x, rb0.y); u.y = pack2(rb0.z, rb0.w);
            u.z = pack2(rb1.x, rb1.y); u.w = pack2(rb1.z, rb1.w);
            *(uint4*)&d[bsto] = u;
            __syncthreads();
        }
    }

#pragma unroll
    for (int mt = 0; mt < 4; mt++) {
        int r0 = m0 + wm * 64 + mt * 16 + gid;
#pragma unroll
        for (int nt = 0; nt < 4; nt++) {
            int col = n0 + wn * 32 + nt * 8 + tg * 2;
            float2 v0 = make_float2(acc[mt][nt][0], acc[mt][nt][1]);
            float2 v1 = make_float2(acc[mt][nt][2], acc[mt][nt][3]);
            if (bias) {
                float2 bv = *(const float2*)(bias + col);
                v0.x += bv.x; v0.y += bv.y; v1.x += bv.x; v1.y += bv.y;
            }
            float* Cp = C + (long)blockIdx.z * cSplit;
            if (resid) {
                float2 q0 = *(const float2*)(resid + (long)r0 * ldc + col);
                float2 q1 = *(const float2*)(resid + (long)(r0 + 8) * ldc + col);
                v0.x += q0.x; v0.y += q0.y; v1.x += q1.x; v1.y += q1.y;
            }
            if (relu) {
                v0.x = fmaxf(v0.x, 0.f); v0.y = fmaxf(v0.y, 0.f);
                v1.x = fmaxf(v1.x, 0.f); v1.y = fmaxf(v1.y, 0.f);
            }
            *(float2*)(Cp + (long)r0 * ldc + col) = v0;
            *(float2*)(Cp + (long)(r0 + 8) * ldc + col) = v1;
        }
    }
}

// ------------------------------------------------------------------
// Small fp16 GEMM (Wf): BM=128, BN=64, BK=32, 256 thr (8 warps 4x2).
// ------------------------------------------------------------------
__global__ __launch_bounds__(256) void gemm16s(
    const __half* __restrict__ A, int lda,
    const float* __restrict__ B, int ldb,
    float* __restrict__ C, int ldc,
    int kIters, int kChunk, long cSplit)
{
    constexpr int ABYTES = 128 * 64;
    constexpr int BBYTES = 32 * 128;
    __shared__ char sm[2][ABYTES + BBYTES];

    const int tid = threadIdx.x;
    const int m0 = blockIdx.y * 128;
    const int n0 = blockIdx.x * 64;
    const int k0 = blockIdx.z * kChunk;
    const int warp = tid >> 5, lane = tid & 31;
    const int wm = warp >> 1, wn = warp & 1;
    const int gid = lane >> 2, tg = lane & 3;

    const __half* aptr[2]; int asto[2];
#pragma unroll
    for (int i = 0; i < 2; i++) {
        int id = tid + i * 256, r = id >> 2, c = id & 3;
        aptr[i] = A + (long)(m0 + r) * lda + k0 + c * 8;
        asto[i] = aoff(r, c);
    }
    const float* bptr; int bsto;
    {
        int k = tid >> 3, c = tid & 7;
        bptr = B + (long)(k0 + k) * ldb + n0 + c * 8;
        bsto = ABYTES + boff<64>(k, c);
    }

    const int aRowL = lane & 15, aChL = lane >> 4;
    uint32_t sbase[2] = { smem_u32(&sm[0][0]), smem_u32(&sm[1][0]) };

    float acc[2][4][4];
#pragma unroll
    for (int i = 0; i < 2; i++)
#pragma unroll
        for (int j = 0; j < 4; j++)
#pragma unroll
            for (int l = 0; l < 4; l++) acc[i][j][l] = 0.f;

    uint4 rau[2]; float4 rb0, rb1;
#pragma unroll
    for (int i = 0; i < 2; i++) rau[i] = *(const uint4*)(aptr[i]);
    rb0 = *(const float4*)(bptr);
    rb1 = *(const float4*)(bptr + 4);
#pragma unroll
    for (int i = 0; i < 2; i++) *(uint4*)&sm[0][asto[i]] = rau[i];
    {
        uint4 u;
        u.x = pack2(rb0.x, rb0.y); u.y = pack2(rb0.z, rb0.w);
        u.z = pack2(rb1.x, rb1.y); u.w = pack2(rb1.z, rb1.w);
        *(uint4*)&sm[0][bsto] = u;
    }
    __syncthreads();

    for (int t = 0; t < kIters; t++) {
        if (t + 1 < kIters) {
            const long ka = (long)(t + 1) * 32;
            const long kbb = (long)(t + 1) * 32 * ldb;
#pragma unroll
            for (int i = 0; i < 2; i++) rau[i] = *(const uint4*)(aptr[i] + ka);
            rb0 = *(const float4*)(bptr + kbb);
            rb1 = *(const float4*)(bptr + kbb + 4);
        }
        const uint32_t sa = sbase[t & 1];
        const uint32_t sbB = sbase[t & 1] + ABYTES;
#pragma unroll
        for (int kk = 0; kk < 2; kk++) {
            uint32_t af[2][4], bf[2][4];
#pragma unroll
            for (int mt = 0; mt < 2; mt++)
                ldsm_x4(af[mt], sa + aoff(wm * 32 + mt * 16 + aRowL, kk * 2 + aChL));
#pragma unroll
            for (int ntp = 0; ntp < 2; ntp++)
                ldsm_x4_t(bf[ntp], sbB + boff<64>(kk * 16 + aRowL,
                                                  wn * 4 + ntp * 2 + aChL));
#pragma unroll
            for (int mt = 0; mt < 2; mt++)
#pragma unroll
                for (int ntp = 0; ntp < 2; ntp++) {
                    mma_fp16(acc[mt][ntp * 2 + 0], af[mt], &bf[ntp][0]);
                    mma_fp16(acc[mt][ntp * 2 + 1], af[mt], &bf[ntp][2]);
                }
        }
        if (t + 1 < kIters) {
            char* d = sm[(t + 1) & 1];
#pragma unroll
            for (int i = 0; i < 2; i++) *(uint4*)&d[asto[i]] = rau[i];
            uint4 u;
            u.x = pack2(rb0.x, rb0.y); u.y = pack2(rb0.z, rb0.w);
            u.z = pack2(rb1.x, rb1.y); u.w = pack2(rb1.z, rb1.w);
            *(uint4*)&d[bsto] = u;
            __syncthreads();
        }
    }

    float* Cp = C + (long)blockIdx.z * cSplit;
#pragma unroll
    for (int mt = 0; mt < 2; mt++) {
        int r0 = m0 + wm * 32 + mt * 16 + gid;
#pragma unroll
        for (int nt = 0; nt < 4; nt++) {
            int col = n0 + wn * 32 + nt * 8 + tg * 2;
            *(float2*)(Cp + (long)r0 * ldc + col) =
                make_float2(acc[mt][nt][0], acc[mt][nt][1]);
            *(float2*)(Cp + (long)(r0 + 8) * ldc + col) =
                make_float2(acc[mt][nt][2], acc[mt][nt][3]);
        }
    }
}

// ------------------------------------------------------------------
// MMA attention per (b,h): 128 threads (4 warps), fp16 in/out, fp32 acc.
// ------------------------------------------------------------------
__global__ __launch_bounds__(128) void attn_mma(
    const __half* __restrict__ Qh, const __half* __restrict__ Kh,
    const __half* __restrict__ Vh, __half* __restrict__ Ctx)
{
    __shared__ __align__(16) char sq[64 * 128], sk[64 * 128], sv[64 * 128];
    const int tid = threadIdx.x;
    const int w = tid >> 5, lane = tid & 31;
    const int gid = lane >> 2, tg = lane & 3;
    const int b = blockIdx.x >> 3, h = blockIdx.x & 7;
    const long base = (long)(b * 64) * 512 + h * 64;

#pragma unroll
    for (int i = 0; i < 4; i++) {
        int id = tid + i * 128, r = id >> 3, c = id & 7;
        int so = foff(r, c);
        const long go = base + (long)r * 512 + c * 8;
        *(uint4*)(sq + so) = *(const uint4*)(Qh + go);
        *(uint4*)(sk + so) = *(const uint4*)(Kh + go);
        *(uint4*)(sv + so) = *(const uint4*)(Vh + go);
    }
    __syncthreads();

    const uint32_t sqb = smem_u32(sq), skb = smem_u32(sk), svb = smem_u32(sv);
    const int rowL = lane & 15, chL = lane >> 4;

    float sacc[8][4];
#pragma unroll
    for (int j = 0; j < 8; j++)
#pragma unroll
        for (int l = 0; l < 4; l++) sacc[j][l] = 0.f;
#pragma unroll
    for (int kk = 0; kk < 4; kk++) {
        uint32_t a[4];
        ldsm_x4(a, sqb + foff(w * 16 + rowL, kk * 2 + chL));
#pragma unroll
        for (int g = 0; g < 4; g++) {
            uint32_t bk[4];
            ldsm_x4(bk, skb + foff(g * 16 + rowL, kk * 2 + chL));
            mma_fp16_2(sacc[g * 2 + 0], a, bk[0], bk[2]);
            mma_fp16_2(sacc[g * 2 + 1], a, bk[1], bk[3]);
        }
    }

    float mx0 = -1e30f, mx1 = -1e30f;
#pragma unroll
    for (int j = 0; j < 8; j++) {
#pragma unroll
        for (int l = 0; l < 4; l++) sacc[j][l] *= 0.125f;
        mx0 = fmaxf(mx0, fmaxf(sacc[j][0], sacc[j][1]));
        mx1 = fmaxf(mx1, fmaxf(sacc[j][2], sacc[j][3]));
    }
#pragma unroll
    for (int o = 1; o < 4; o <<= 1) {
        mx0 = fmaxf(mx0, __shfl_xor_sync(~0u, mx0, o));
        mx1 = fmaxf(mx1, __shfl_xor_sync(~0u, mx1, o));
    }
    float s0 = 0.f, s1 = 0.f;
#pragma unroll
    for (int j = 0; j < 8; j++) {
        sacc[j][0] = __expf(sacc[j][0] - mx0);
        sacc[j][1] = __expf(sacc[j][1] - mx0);
        sacc[j][2] = __expf(sacc[j][2] - mx1);
        sacc[j][3] = __expf(sacc[j][3] - mx1);
        s0 += sacc[j][0] + sacc[j][1];
        s1 += sacc[j][2] + sacc[j][3];
    }
#pragma unroll
    for (int o = 1; o < 4; o <<= 1) {
        s0 += __shfl_xor_sync(~0u, s0, o);
        s1 += __shfl_xor_sync(~0u, s1, o);
    }
    const float r0 = 1.f / s0, r1 = 1.f / s1;

    uint32_t ap[4][4];
#pragma unroll
    for (int kk = 0; kk < 4; kk++) {
        ap[kk][0] = pack2(sacc[kk * 2][0], sacc[kk * 2][1]);
        ap[kk][1] = pack2(sacc[kk * 2][2], sacc[kk * 2][3]);
        ap[kk][2] = pack2(sacc[kk * 2 + 1][0], sacc[kk * 2 + 1][1]);
        ap[kk][3] = pack2(sacc[kk * 2 + 1][2], sacc[kk * 2 + 1][3]);
    }

    float cacc[8][4];
#pragma unroll
    for (int j = 0; j < 8; j++)
#pragma unroll
        for (int l = 0; l < 4; l++) cacc[j][l] = 0.f;
#pragma unroll
    for (int kk = 0; kk < 4; kk++) {
#pragma unroll
        for (int g = 0; g < 4; g++) {
            uint32_t bv[4];
            ldsm_x4_t(bv, svb + foff(kk * 16 + rowL, g * 2 + chL));
            mma_fp16_2(cacc[g * 2 + 0], ap[kk], bv[0], bv[1]);
            mma_fp16_2(cacc[g * 2 + 1], ap[kk], bv[2], bv[3]);
        }
    }

    const long orow0 = (long)(b * 64 + w * 16 + gid) * 512 + h * 64;
    const long orow1 = orow0 + 8 * 512;
#pragma unroll
    for (int nt = 0; nt < 8; nt++) {
        int col = nt * 8 + tg * 2;
        *(__half2*)(Ctx + orow0 + col) = __floats2half2_rn(cacc[nt][0] * r0, cacc[nt][1] * r0);
        *(__half2*)(Ctx + orow1 + col) = __floats2half2_rn(cacc[nt][2] * r1, cacc[nt][3] * r1);
    }
}

// ---------------- fp32 -> fp16 bulk convert (grid = n/1024) ----------------
__global__ void cvt_f2h(const float* __restrict__ in, __half* __restrict__ out)
{
    int idx = blockIdx.x * 256 + threadIdx.x;
    float4 f = ((const float4*)in)[idx];
    __half2* o = (__half2*)out + idx * 2;
    o[0] = __floats2half2_rn(f.x, f.y);
    o[1] = __floats2half2_rn(f.z, f.w);
}

// ---------------- LayerNorm width=512, dual fp32+fp16 out ----------------
__global__ __launch_bounds__(256) void ln512_dual(
    const float* __restrict__ in, float* __restrict__ out, __half* __restrict__ outh,
    const float* __restrict__ gam, const float* __restrict__ bet)
{
    const int row = blockIdx.x * 8 + (threadIdx.x >> 5);
    const int lane = threadIdx.x & 31;
    const float* p = in + (long)row * 512;
    float v[16], s = 0.f, s2 = 0.f;
#pragma unroll
    for (int i = 0; i < 16; i++) {
        v[i] = p[lane + 32 * i]; s += v[i]; s2 = fmaf(v[i], v[i], s2);
    }
#pragma unroll
    for (int o = 16; o > 0; o >>= 1) {
        s += __shfl_xor_sync(~0u, s, o); s2 += __shfl_xor_sync(~0u, s2, o);
    }
    float mu = s * (1.f / 512.f);
    float rsg = rsqrtf(s2 * (1.f / 512.f) - mu * mu + 1e-5f);
    float* q = out + (long)row * 512;
    __half* qh = outh + (long)row * 512;
#pragma unroll
    for (int i = 0; i < 16; i++) {
        int c = lane + 32 * i;
        float r = (v[i] - mu) * rsg * gam[c] + bet[c];
        q[c] = r;
        qh[c] = __float2half_rn(r);
    }
}

// ---------------- LayerNorm width=32768, fp16 out ----------------
__global__ __launch_bounds__(1024) void ln32k_h(
    const float* __restrict__ in, __half* __restrict__ out,
    const float* __restrict__ gam, const float* __restrict__ bet)
{
    __shared__ float rs1[32], rs2[32], stat[2];
    const int row = blockIdx.x;
    const float* p = in + (long)row * 32768;
    float s = 0.f, s2 = 0.f;
    for (int i = threadIdx.x; i < 32768; i += 1024) {
        float v = p[i]; s += v; s2 = fmaf(v, v, s2);
    }
#pragma unroll
    for (int o = 16; o > 0; o >>= 1) {
        s += __shfl_xor_sync(~0u, s, o); s2 += __shfl_xor_sync(~0u, s2, o);
    }
    if ((threadIdx.x & 31) == 0) { rs1[threadIdx.x >> 5] = s; rs2[threadIdx.x >> 5] = s2; }
    __syncthreads();
    if (threadIdx.x < 32) {
        s = rs1[threadIdx.x]; s2 = rs2[threadIdx.x];
#pragma unroll
        for (int o = 16; o > 0; o >>= 1) {
            s += __shfl_xor_sync(~0u, s, o); s2 += __shfl_xor_sync(~0u, s2, o);
        }
        if (threadIdx.x == 0) {
            float mu = s * (1.f / 32768.f);
            stat[0] = mu; stat[1] = rsqrtf(s2 * (1.f / 32768.f) - mu * mu + 1e-5f);
        }
    }
    __syncthreads();
    float mu = stat[0], rsg = stat[1];
    __half* q = out + (long)row * 32768;
    for (int i = threadIdx.x; i < 32768; i += 1024)
        q[i] = __float2half_rn((p[i] - mu) * rsg * gam[i] + bet[i]);
}

// ---------------- reducers ----------------
__global__ void reduce16_relu_h(const float* __restrict__ part,
                                const float* __restrict__ b1, __half* __restrict__ out)
{
    int idx = blockIdx.x * 256 + threadIdx.x;  // < 524288
    float s = 0.f;
#pragma unroll
    for (int z = 0; z < 16; z++) s += part[(long)z * 524288 + idx];
    s += b1[idx & 2047];
    out[idx] = __float2half_rn(fmaxf(s, 0.f));
}

__global__ void reduce_out_k(const float* __restrict__ part,
                             const float* __restrict__ bf, float* __restrict__ out)
{
    int idx = blockIdx.x * 256 + threadIdx.x;
    if (idx >= 12800) return;
    int m = idx / 50, j = idx % 50;
    float s = bf[j];
#pragma unroll
    for (int z = 0; z < 64; z++) s += part[(long)z * 16384 + m * 64 + j];
    out[idx] = s;
}

__global__ void pad_wf_k(const float* __restrict__ Wf, float* __restrict__ Wfp)
{
    int idx = blockIdx.x * 256 + threadIdx.x;  // < 32768*64
    int k = idx >> 6, j = idx & 63;
    Wfp[idx] = (j < 50) ? Wf[k * 50 + j] : 0.f;
}

// ------------------------------------------------------------------
extern "C" void kernel_launch(void* const* d_in, const int* in_sizes, int n_in,
                              void* d_out, int out_size)
{
    const float* inputs = (const float*)d_in[0];
    const float* Wq = (const float*)d_in[1];  const float* bq = (const float*)d_in[2];
    const float* Wk = (const float*)d_in[3];  const float* bk = (const float*)d_in[4];
    const float* Wv = (const float*)d_in[5];  const float* bv = (const float*)d_in[6];
    const float* Wo = (const float*)d_in[7];  const float* bo = (const float*)d_in[8];
    const float* ln1g = (const float*)d_in[9];  const float* ln1b = (const float*)d_in[10];
    const float* W1 = (const float*)d_in[11]; const float* b1 = (const float*)d_in[12];
    const float* W2 = (const float*)d_in[13]; const float* b2 = (const float*)d_in[14];
    const float* ln2g = (const float*)d_in[15]; const float* ln2b = (const float*)d_in[16];
    const float* Wf = (const float*)d_in[17]; const float* bf = (const float*)d_in[18];
    float* out = (float*)d_out;

    __half *inh, *qh, *kh, *vh, *ctxh, *xh, *hh, *yh, *wqh, *wkh, *wvh, *woh;
    float *res1, *x, *p4, *v2, *wfp, *p6;
    cudaGetSymbolAddress((void**)&inh, g_inh);
    cudaGetSymbolAddress((void**)&qh, g_qh);
    cudaGetSymbolAddress((void**)&kh, g_kh);
    cudaGetSymbolAddress((void**)&vh, g_vh);
    cudaGetSymbolAddress((void**)&ctxh, g_ctxh);
    cudaGetSymbolAddress((void**)&xh, g_xh);
    cudaGetSymbolAddress((void**)&hh, g_hh);
    cudaGetSymbolAddress((void**)&yh, g_yh);
    cudaGetSymbolAddress((void**)&wqh, g_wqh);
    cudaGetSymbolAddress((void**)&wkh, g_wkh);
    cudaGetSymbolAddress((void**)&wvh, g_wvh);
    cudaGetSymbolAddress((void**)&woh, g_woh);
    cudaGetSymbolAddress((void**)&res1, g_res1);
    cudaGetSymbolAddress((void**)&x, g_x);
    cudaGetSymbolAddress((void**)&p4, g_p4);
    cudaGetSymbolAddress((void**)&v2, g_v2);
    cudaGetSymbolAddress((void**)&wfp, g_wfp);
    cudaGetSymbolAddress((void**)&p6, g_p6);

    constexpr int GSMEM = 4 * 24576;   // 96 KB dynamic
    cudaFuncSetAttribute(gemma<true>, cudaFuncAttributeMaxDynamicSharedMemorySize, GSMEM);
    cudaFuncSetAttribute(gemma<false>, cudaFuncAttributeMaxDynamicSharedMemorySize, GSMEM);

    // independent prep
    pad_wf_k<<<8192, 256>>>(Wf, wfp);
    cvt_f2h<<<8192, 256>>>(inputs, inh);
    cvt_f2h<<<256, 256>>>(Wq, wqh);   // 8*512*64 = 262144
    cvt_f2h<<<256, 256>>>(Wk, wkh);
    cvt_f2h<<<256, 256>>>(Wv, wvh);
    cvt_f2h<<<256, 256>>>(Wo, woh);

    // QKV projections -> fp16 outputs (cp.async pipeline)
    gemma<true><<<dim3(4, 64), 512, GSMEM>>>(inh, 512, wqh, 64, 32768,
                                             qh, 512, 16, bq, nullptr);
    gemma<true><<<dim3(4, 64), 512, GSMEM>>>(inh, 512, wkh, 64, 32768,
                                             kh, 512, 16, bk, nullptr);
    gemma<true><<<dim3(4, 64), 512, GSMEM>>>(inh, 512, wvh, 64, 32768,
                                             vh, 512, 16, bv, nullptr);

    // MMA attention
    attn_mma<<<2048, 128>>>(qh, kh, vh, ctxh);

    // output projection + bias + residual(inputs) -> fp32
    gemma<false><<<dim3(4, 64), 512, GSMEM>>>(ctxh, 512, woh, 512, 0,
                                              res1, 512, 16, bo, inputs);

    // LN1 -> x (fp32) + xh (fp16)
    ln512_dual<<<2048, 256>>>(res1, x, xh, ln1g, ln1b);

    // h = relu(x @ W1 + b1): split-K 16
    gemm512<<<dim3(16, 1, 16), 512>>>(xh, 32768, W1, 2048,
                                      p4, 2048, 64, 2048, 524288,
                                      nullptr, nullptr, 0);
    reduce16_relu_h<<<2048, 256>>>(p4, b1, hh);

    // v2 = h @ W2 + b2 + x -> fp32
    gemm512<<<dim3(256, 1, 1), 512>>>(hh, 2048, W2, 32768,
                                      v2, 32768, 64, 0, 0, b2, x, 0);

    // LN2 -> yh fp16
    ln32k_h<<<256, 1024>>>(v2, yh, ln2g, ln2b);

    // logits: y @ wfp split-K 64
    gemm16s<<<dim3(1, 2, 64), 256>>>(yh, 32768, wfp, 64, p6, 64, 16, 512, 16384);
    reduce_out_k<<<50, 256>>>(p6, bf, out);
}